// round 5
// baseline (speedup 1.0000x reference)
#include <cuda_runtime.h>
#include <cuda_bf16.h>
#include <stdint.h>

// ---------------------------------------------------------------------------
// Problem constants
// ---------------------------------------------------------------------------
#define BB   2
#define HH   12
#define DD   64
#define EE   768
#define QLL  1024
#define KLL  2048
#define HDD  768
#define SCALEF 0.125f
typedef int mask_t;   // harness widens bool -> int32
typedef unsigned short u16;

// ---------------------------------------------------------------------------
// Scratch (device globals)
// ---------------------------------------------------------------------------
__device__ u16 g_qw_h[(size_t)BB * QLL * HDD];   // bf16(q + r_w_bias) hi
__device__ u16 g_qw_l[(size_t)BB * QLL * HDD];
__device__ u16 g_qr_h[(size_t)BB * QLL * HDD];   // bf16(q + r_r_bias) hi
__device__ u16 g_qr_l[(size_t)BB * QLL * HDD];
__device__ u16 g_k_h [(size_t)BB * KLL * HDD];
__device__ u16 g_k_l [(size_t)BB * KLL * HDD];
__device__ u16 g_v_h [(size_t)BB * KLL * HDD];
__device__ u16 g_v_l [(size_t)BB * KLL * HDD];
__device__ u16 g_r_h [(size_t)KLL * HDD];
__device__ u16 g_r_l [(size_t)KLL * HDD];
__device__ float g_s  [(size_t)BB * HH * QLL * KLL];
__device__ float g_m  [(size_t)BB * HH * QLL];
__device__ float g_l  [(size_t)BB * HH * QLL];
__device__ float g_vec[(size_t)BB * QLL * HDD];

// ---------------------------------------------------------------------------
// Warp-level tensor-core primitives (plain sm_103 target: mma.sync + ldmatrix)
// ---------------------------------------------------------------------------
__device__ __forceinline__ uint32_t smem_u32(const void* p) {
    uint32_t a;
    asm("{ .reg .u64 t; cvta.to.shared.u64 t, %1; cvt.u32.u64 %0, t; }" : "=r"(a) : "l"(p));
    return a;
}
__device__ __forceinline__ void ldsm4(uint32_t& r0, uint32_t& r1, uint32_t& r2, uint32_t& r3,
                                      uint32_t a) {
    asm volatile("ldmatrix.sync.aligned.m8n8.x4.shared.b16 {%0,%1,%2,%3}, [%4];"
                 : "=r"(r0), "=r"(r1), "=r"(r2), "=r"(r3) : "r"(a));
}
__device__ __forceinline__ void mma16816(float* c, const uint32_t* a, const uint32_t* b) {
    asm volatile("mma.sync.aligned.m16n8k16.row.col.f32.bf16.bf16.f32 "
                 "{%0,%1,%2,%3}, {%4,%5,%6,%7}, {%8,%9}, {%0,%1,%2,%3};"
                 : "+f"(c[0]), "+f"(c[1]), "+f"(c[2]), "+f"(c[3])
                 : "r"(a[0]), "r"(a[1]), "r"(a[2]), "r"(a[3]), "r"(b[0]), "r"(b[1]));
}
__device__ __forceinline__ void split_bf16(float x, u16& h, u16& l) {
    __nv_bfloat16 hb = __float2bfloat16(x);
    h = __bfloat16_as_ushort(hb);
    l = __bfloat16_as_ushort(__float2bfloat16(x - __bfloat162float(hb)));
}
__device__ __forceinline__ void split4(float4 v, uint2& hi, uint2& lo) {
    u16 h0, h1, h2, h3, l0, l1, l2, l3;
    split_bf16(v.x, h0, l0); split_bf16(v.y, h1, l1);
    split_bf16(v.z, h2, l2); split_bf16(v.w, h3, l3);
    hi = make_uint2((uint32_t)h0 | ((uint32_t)h1 << 16), (uint32_t)h2 | ((uint32_t)h3 << 16));
    lo = make_uint2((uint32_t)l0 | ((uint32_t)l1 << 16), (uint32_t)l2 | ((uint32_t)l3 << 16));
}

// ---------------------------------------------------------------------------
// tgemm: C[M,N] = A[M,K] * B^T + bias.  A row-major (lda); B(n,k) at B[k*ldb+n].
// Block tile 128x64, K-slab 64, 8 warps (4m x 2n), warp tile 32x32.
// Epilogue modes:
//   0: Cf fp32 = v
//   1: (C1h,C1l) = split_bf16(v)
//   2: (C1h,C1l) = split(v + add1[c]); (C2h,C2l) = split(v + add2[c])
// where v = acc + bias[c] (bias may be null).
// ---------------------------------------------------------------------------
#define GP 144
#define SM_AHI 0
#define SM_ALO (128 * GP)
#define SM_BHI (2 * 128 * GP)
#define SM_BLO (2 * 128 * GP + 64 * GP)
#define SM_G_TOTAL (2 * 128 * GP + 2 * 64 * GP)   // 55296

__global__ void __launch_bounds__(256, 2)
tgemm(const float* __restrict__ Ag, long lda, long sAb, long sAh,
      const float* __restrict__ Bg, long ldb, long sBb, long sBh,
      const float* __restrict__ bias, int mode,
      float* __restrict__ Cf, u16* __restrict__ C1h, u16* __restrict__ C1l,
      u16* __restrict__ C2h, u16* __restrict__ C2l,
      const float* __restrict__ add1, const float* __restrict__ add2,
      long ldc, long sCb, long sCh, int K, int nh)
{
    extern __shared__ char sm[];
    const uint32_t sb = smem_u32(sm);
    const int tid = threadIdx.x, wid = tid >> 5, lane = tid & 31;
    const int mw = wid >> 1, nw = wid & 1;
    const int zb = blockIdx.z / nh, zh = blockIdx.z % nh;
    const float* A = Ag + (size_t)zb * sAb + (size_t)zh * sAh;
    const float* B = Bg + (size_t)zb * sBb + (size_t)zh * sBh;
    const int m0 = blockIdx.y << 7;
    const int n0 = blockIdx.x << 6;

    float acc[2][4][4] = {};

    const int nslab = K >> 6;
    for (int s = 0; s < nslab; s++) {
        const int k0 = s << 6;
        #pragma unroll
        for (int it = 0; it < 8; it++) {
            int idx = (it * 256 + tid) << 2;
            int m = idx >> 6, k = idx & 63;
            float4 a = *reinterpret_cast<const float4*>(A + (size_t)(m0 + m) * lda + (k0 + k));
            uint2 hi, lo; split4(a, hi, lo);
            int off = m * GP + k * 2;
            *reinterpret_cast<uint2*>(sm + SM_AHI + off) = hi;
            *reinterpret_cast<uint2*>(sm + SM_ALO + off) = lo;
        }
        #pragma unroll
        for (int it = 0; it < 16; it++) {
            int idx = it * 256 + tid;
            int k = idx >> 6, n = idx & 63;
            float b = B[(size_t)(k0 + k) * ldb + (n0 + n)];
            u16 h, l; split_bf16(b, h, l);
            int off = n * GP + k * 2;
            *reinterpret_cast<u16*>(sm + SM_BHI + off) = h;
            *reinterpret_cast<u16*>(sm + SM_BLO + off) = l;
        }
        __syncthreads();

        #pragma unroll
        for (int ks = 0; ks < 4; ks++) {
            const int kc = ks << 4;
            uint32_t ah[2][4], al[2][4], bh[4][2], bl[4][2];
            #pragma unroll
            for (int i = 0; i < 2; i++) {
                int row = mw * 32 + i * 16 + (lane & 15);
                int col = kc + ((lane >> 4) << 3);
                uint32_t off = (uint32_t)(row * GP + col * 2);
                ldsm4(ah[i][0], ah[i][1], ah[i][2], ah[i][3], sb + SM_AHI + off);
                ldsm4(al[i][0], al[i][1], al[i][2], al[i][3], sb + SM_ALO + off);
            }
            #pragma unroll
            for (int jj = 0; jj < 2; jj++) {
                int n = nw * 32 + jj * 16 + ((lane >> 4) << 3) + (lane & 7);
                int k = kc + (((lane >> 3) & 1) << 3);
                uint32_t off = (uint32_t)(n * GP + k * 2);
                ldsm4(bh[jj*2][0], bh[jj*2][1], bh[jj*2+1][0], bh[jj*2+1][1], sb + SM_BHI + off);
                ldsm4(bl[jj*2][0], bl[jj*2][1], bl[jj*2+1][0], bl[jj*2+1][1], sb + SM_BLO + off);
            }
            #pragma unroll
            for (int i = 0; i < 2; i++)
                #pragma unroll
                for (int j = 0; j < 4; j++) {
                    mma16816(acc[i][j], ah[i], bh[j]);
                    mma16816(acc[i][j], ah[i], bl[j]);
                    mma16816(acc[i][j], al[i], bh[j]);
                }
        }
        __syncthreads();
    }

    // Epilogue
    const int gid = lane >> 2, tg = lane & 3;
    #pragma unroll
    for (int i = 0; i < 2; i++)
        #pragma unroll
        for (int j = 0; j < 4; j++) {
            int c = n0 + nw * 32 + j * 8 + tg * 2;
            float b0 = bias ? bias[c] : 0.f;
            float b1 = bias ? bias[c + 1] : 0.f;
            #pragma unroll
            for (int eh = 0; eh < 2; eh++) {
                int r = m0 + mw * 32 + i * 16 + gid + 8 * eh;
                size_t base = (size_t)zb * sCb + (size_t)zh * sCh + (size_t)r * ldc + c;
                float v0 = acc[i][j][eh * 2 + 0] + b0;
                float v1 = acc[i][j][eh * 2 + 1] + b1;
                if (mode == 0) {
                    *reinterpret_cast<float2*>(Cf + base) = make_float2(v0, v1);
                } else if (mode == 1) {
                    u16 h0, l0, h1, l1;
                    split_bf16(v0, h0, l0); split_bf16(v1, h1, l1);
                    *reinterpret_cast<uint32_t*>(C1h + base) = (uint32_t)h0 | ((uint32_t)h1 << 16);
                    *reinterpret_cast<uint32_t*>(C1l + base) = (uint32_t)l0 | ((uint32_t)l1 << 16);
                } else {
                    u16 h0, l0, h1, l1;
                    split_bf16(v0 + add1[c], h0, l0); split_bf16(v1 + add1[c + 1], h1, l1);
                    *reinterpret_cast<uint32_t*>(C1h + base) = (uint32_t)h0 | ((uint32_t)h1 << 16);
                    *reinterpret_cast<uint32_t*>(C1l + base) = (uint32_t)l0 | ((uint32_t)l1 << 16);
                    split_bf16(v0 + add2[c], h0, l0); split_bf16(v1 + add2[c + 1], h1, l1);
                    *reinterpret_cast<uint32_t*>(C2h + base) = (uint32_t)h0 | ((uint32_t)h1 << 16);
                    *reinterpret_cast<uint32_t*>(C2l + base) = (uint32_t)l0 | ((uint32_t)l1 << 16);
                }
            }
        }
}

// ---------------------------------------------------------------------------
// tscore: scores + online softmax stats.
// A'[m,0:64] = qw(b3,h3); A'[m,64:128] = qr(bu,hm1) (or 0).  (bf16 precomputed)
// B'[n,0:64] = k(b3,h3);  B'[n,64:128] = r(hm1)      (or 0).
// Per k-tile: s = mask ? -1e9 : acc*SCALE -> g_s; online row max m / sum l.
// ---------------------------------------------------------------------------
#define SP 272
#define SS_AHI 0
#define SS_ALO (128 * SP)
#define SS_BHI (2 * 128 * SP)
#define SS_BLO (2 * 128 * SP + 64 * SP)
#define SS_RED (2 * 128 * SP + 2 * 64 * SP)          // 104448
#define SS_MRUN (SS_RED)
#define SS_LRUN (SS_RED + 512)
#define SS_M0   (SS_RED + 1024)
#define SS_M1   (SS_RED + 1536)
#define SS_S0   (SS_RED + 2048)
#define SS_S1   (SS_RED + 2560)
#define SS_TOTAL (SS_RED + 3072)                      // 107520

__global__ void __launch_bounds__(256)
tscore(const mask_t* __restrict__ mask)
{
    extern __shared__ char sm[];
    const uint32_t sb = smem_u32(sm);
    float* mrun = reinterpret_cast<float*>(sm + SS_MRUN);
    float* lrun = reinterpret_cast<float*>(sm + SS_LRUN);
    float* rM0  = reinterpret_cast<float*>(sm + SS_M0);
    float* rM1  = reinterpret_cast<float*>(sm + SS_M1);
    float* rS0  = reinterpret_cast<float*>(sm + SS_S0);
    float* rS1  = reinterpret_cast<float*>(sm + SS_S1);

    const int tid = threadIdx.x, wid = tid >> 5, lane = tid & 31;
    const int mw = wid >> 1, nw = wid & 1;
    const int gid = lane >> 2, tg = lane & 3;
    const int bh = blockIdx.z;
    const int b3 = bh / HH, h3 = bh % HH;
    const int mp = bh + BB;
    const int bu = mp / (HH + 1), hh = mp % (HH + 1);
    const int has_bd = (hh != 0);
    const int hm1 = hh - 1;
    const int q0 = blockIdx.y << 7;

    if (tid < 128) { mrun[tid] = -3.0e38f; lrun[tid] = 0.f; }

    // A' fill (128 x 128) from precomputed bf16
    #pragma unroll
    for (int it = 0; it < 16; it++) {
        int idx = (it * 256 + tid) << 2;
        int m = idx >> 7, d = idx & 127;
        uint2 hi, lo;
        if (d < 64) {
            size_t base = (size_t)(b3 * QLL + q0 + m) * HDD + h3 * DD + d;
            hi = *reinterpret_cast<const uint2*>(g_qw_h + base);
            lo = *reinterpret_cast<const uint2*>(g_qw_l + base);
        } else if (has_bd) {
            size_t base = (size_t)(bu * QLL + q0 + m) * HDD + hm1 * DD + (d - 64);
            hi = *reinterpret_cast<const uint2*>(g_qr_h + base);
            lo = *reinterpret_cast<const uint2*>(g_qr_l + base);
        } else {
            hi = make_uint2(0u, 0u); lo = make_uint2(0u, 0u);
        }
        int off = m * SP + d * 2;
        *reinterpret_cast<uint2*>(sm + SS_AHI + off) = hi;
        *reinterpret_cast<uint2*>(sm + SS_ALO + off) = lo;
    }
    __syncthreads();

    for (int kt = 0; kt < 32; kt++) {
        const int kc = kt << 6;
        // B' fill (64 x 128) from precomputed bf16
        #pragma unroll
        for (int it = 0; it < 8; it++) {
            int idx = (it * 256 + tid) << 2;
            int n = idx >> 7, d = idx & 127;
            uint2 hi, lo;
            if (d < 64) {
                size_t base = (size_t)(b3 * KLL + kc + n) * HDD + h3 * DD + d;
                hi = *reinterpret_cast<const uint2*>(g_k_h + base);
                lo = *reinterpret_cast<const uint2*>(g_k_l + base);
            } else if (has_bd) {
                size_t base = (size_t)(kc + n) * HDD + hm1 * DD + (d - 64);
                hi = *reinterpret_cast<const uint2*>(g_r_h + base);
                lo = *reinterpret_cast<const uint2*>(g_r_l + base);
            } else {
                hi = make_uint2(0u, 0u); lo = make_uint2(0u, 0u);
            }
            int off = n * SP + d * 2;
            *reinterpret_cast<uint2*>(sm + SS_BHI + off) = hi;
            *reinterpret_cast<uint2*>(sm + SS_BLO + off) = lo;
        }
        __syncthreads();

        float acc[2][4][4] = {};
        #pragma unroll
        for (int ks = 0; ks < 8; ks++) {
            const int kcc = ks << 4;
            uint32_t ah[2][4], al[2][4], bh[4][2], bl[4][2];
            #pragma unroll
            for (int i = 0; i < 2; i++) {
                int row = mw * 32 + i * 16 + (lane & 15);
                int col = kcc + ((lane >> 4) << 3);
                uint32_t off = (uint32_t)(row * SP + col * 2);
                ldsm4(ah[i][0], ah[i][1], ah[i][2], ah[i][3], sb + SS_AHI + off);
                ldsm4(al[i][0], al[i][1], al[i][2], al[i][3], sb + SS_ALO + off);
            }
            #pragma unroll
            for (int jj = 0; jj < 2; jj++) {
                int n = nw * 32 + jj * 16 + ((lane >> 4) << 3) + (lane & 7);
                int k = kcc + (((lane >> 3) & 1) << 3);
                uint32_t off = (uint32_t)(n * SP + k * 2);
                ldsm4(bh[jj*2][0], bh[jj*2][1], bh[jj*2+1][0], bh[jj*2+1][1], sb + SS_BHI + off);
                ldsm4(bl[jj*2][0], bl[jj*2][1], bl[jj*2+1][0], bl[jj*2+1][1], sb + SS_BLO + off);
            }
            #pragma unroll
            for (int i = 0; i < 2; i++)
                #pragma unroll
                for (int j = 0; j < 4; j++) {
                    mma16816(acc[i][j], ah[i], bh[j]);
                    mma16816(acc[i][j], ah[i], bl[j]);
                    mma16816(acc[i][j], al[i], bh[j]);
                }
        }

        // Mask + scale in registers; write g_s
        #pragma unroll
        for (int i = 0; i < 2; i++)
            #pragma unroll
            for (int j = 0; j < 4; j++) {
                int q = q0 + mw * 32 + i * 16 + gid;
                int c = kc + nw * 32 + j * 8 + tg * 2;
                const size_t mrow0 = (size_t)(b3 * QLL + q) * KLL + c;
                const size_t srow0 = ((size_t)bh * QLL + q) * KLL + c;
                int2 mk = *reinterpret_cast<const int2*>(mask + mrow0);
                acc[i][j][0] = mk.x ? -1e9f : acc[i][j][0] * SCALEF;
                acc[i][j][1] = mk.y ? -1e9f : acc[i][j][1] * SCALEF;
                *reinterpret_cast<float2*>(g_s + srow0) = make_float2(acc[i][j][0], acc[i][j][1]);
                mk = *reinterpret_cast<const int2*>(mask + mrow0 + 8 * KLL);
                acc[i][j][2] = mk.x ? -1e9f : acc[i][j][2] * SCALEF;
                acc[i][j][3] = mk.y ? -1e9f : acc[i][j][3] * SCALEF;
                *reinterpret_cast<float2*>(g_s + srow0 + 8 * KLL) = make_float2(acc[i][j][2], acc[i][j][3]);
            }

        // --- online max ---
        float tmax[4];
        #pragma unroll
        for (int r = 0; r < 4; r++) tmax[r] = -3.0e38f;
        #pragma unroll
        for (int i = 0; i < 2; i++)
            #pragma unroll
            for (int j = 0; j < 4; j++)
                #pragma unroll
                for (int e = 0; e < 4; e++) {
                    int r = i * 2 + (e >> 1);
                    tmax[r] = fmaxf(tmax[r], acc[i][j][e]);
                }
        #pragma unroll
        for (int r = 0; r < 4; r++) {
            tmax[r] = fmaxf(tmax[r], __shfl_xor_sync(0xffffffffu, tmax[r], 1));
            tmax[r] = fmaxf(tmax[r], __shfl_xor_sync(0xffffffffu, tmax[r], 2));
        }
        if (tg == 0) {
            float* dst = nw ? rM1 : rM0;
            #pragma unroll
            for (int r = 0; r < 4; r++) {
                int row = mw * 32 + (r >> 1) * 16 + 8 * (r & 1) + gid;
                dst[row] = tmax[r];
            }
        }
        __syncthreads();

        float mnew[4], mold[4];
        #pragma unroll
        for (int r = 0; r < 4; r++) {
            int row = mw * 32 + (r >> 1) * 16 + 8 * (r & 1) + gid;
            mold[r] = mrun[row];
            mnew[r] = fmaxf(mold[r], fmaxf(rM0[row], rM1[row]));
        }

        // --- sum of exp(tile) at mnew ---
        float tsum[4] = {0.f, 0.f, 0.f, 0.f};
        #pragma unroll
        for (int i = 0; i < 2; i++)
            #pragma unroll
            for (int j = 0; j < 4; j++)
                #pragma unroll
                for (int e = 0; e < 4; e++) {
                    int r = i * 2 + (e >> 1);
                    tsum[r] += __expf(acc[i][j][e] - mnew[r]);
                }
        #pragma unroll
        for (int r = 0; r < 4; r++) {
            tsum[r] += __shfl_xor_sync(0xffffffffu, tsum[r], 1);
            tsum[r] += __shfl_xor_sync(0xffffffffu, tsum[r], 2);
        }
        __syncthreads();     // rM reads done before rS reuse barrier
        if (tg == 0) {
            float* dst = nw ? rS1 : rS0;
            #pragma unroll
            for (int r = 0; r < 4; r++) {
                int row = mw * 32 + (r >> 1) * 16 + 8 * (r & 1) + gid;
                dst[row] = tsum[r];
            }
        }
        __syncthreads();
        if (nw == 0 && tg == 0) {
            #pragma unroll
            for (int r = 0; r < 4; r++) {
                int row = mw * 32 + (r >> 1) * 16 + 8 * (r & 1) + gid;
                lrun[row] = lrun[row] * __expf(mold[r] - mnew[r]) + rS0[row] + rS1[row];
                mrun[row] = mnew[r];
            }
        }
        __syncthreads();
    }

    if (tid < 128) {
        g_m[(size_t)bh * QLL + q0 + tid] = mrun[tid];
        g_l[(size_t)bh * QLL + q0 + tid] = lrun[tid];
    }
}

// ---------------------------------------------------------------------------
// probpv: p = exp(s - m) / l  -> prob (output), and vec = p @ V_h (MMA fused).
// Block = (bh, 128-q tile); loops 32 key tiles of 64.
// ---------------------------------------------------------------------------
#define PP_SMM (SM_G_TOTAL)
#define PP_SML (SM_G_TOTAL + 512)
#define PP_TOTAL (SM_G_TOTAL + 1024)

__global__ void __launch_bounds__(256)
probpv(float* __restrict__ prob)
{
    extern __shared__ char sm[];
    const uint32_t sb = smem_u32(sm);
    float* smM = reinterpret_cast<float*>(sm + PP_SMM);
    float* smL = reinterpret_cast<float*>(sm + PP_SML);

    const int tid = threadIdx.x, wid = tid >> 5, lane = tid & 31;
    const int mw = wid >> 1, nw = wid & 1;
    const int bh = blockIdx.z;
    const int b3 = bh / HH, h3 = bh % HH;
    const int q0 = blockIdx.y << 7;

    if (tid < 128) {
        smM[tid] = g_m[(size_t)bh * QLL + q0 + tid];
        smL[tid] = 1.0f / g_l[(size_t)bh * QLL + q0 + tid];
    }
    __syncthreads();

    float acc[2][4][4] = {};

    for (int kt = 0; kt < 32; kt++) {
        const int kc = kt << 6;
        // p tile: read s, exp-normalize, write prob, split to smem (A layout)
        #pragma unroll
        for (int it = 0; it < 8; it++) {
            int idx = (it * 256 + tid) << 2;
            int m = idx >> 6, k = idx & 63;
            const size_t gbase = ((size_t)bh * QLL + q0 + m) * KLL + kc + k;
            float4 s4 = *reinterpret_cast<const float4*>(g_s + gbase);
            const float mm = smM[m], li = smL[m];
            float4 p4;
            p4.x = __expf(s4.x - mm) * li;
            p4.y = __expf(s4.y - mm) * li;
            p4.z = __expf(s4.z - mm) * li;
            p4.w = __expf(s4.w - mm) * li;
            *reinterpret_cast<float4*>(prob + gbase) = p4;
            uint2 hi, lo; split4(p4, hi, lo);
            int off = m * GP + k * 2;
            *reinterpret_cast<uint2*>(sm + SM_AHI + off) = hi;
            *reinterpret_cast<uint2*>(sm + SM_ALO + off) = lo;
        }
        // V tile (precomputed bf16): B(n,k) = v[(kc+k)*HDD + h3*64 + n]
        #pragma unroll
        for (int it = 0; it < 16; it++) {
            int idx = it * 256 + tid;
            int k = idx >> 6, n = idx & 63;
            size_t base = (size_t)(b3 * KLL + kc + k) * HDD + h3 * DD + n;
            int off = n * GP + k * 2;
            *reinterpret_cast<u16*>(sm + SM_BHI + off) = g_v_h[base];
            *reinterpret_cast<u16*>(sm + SM_BLO + off) = g_v_l[base];
        }
        __syncthreads();

        #pragma unroll
        for (int ks = 0; ks < 4; ks++) {
            const int kcc = ks << 4;
            uint32_t ah[2][4], al[2][4], bh_[4][2], bl_[4][2];
            #pragma unroll
            for (int i = 0; i < 2; i++) {
                int row = mw * 32 + i * 16 + (lane & 15);
                int col = kcc + ((lane >> 4) << 3);
                uint32_t off = (uint32_t)(row * GP + col * 2);
                ldsm4(ah[i][0], ah[i][1], ah[i][2], ah[i][3], sb + SM_AHI + off);
                ldsm4(al[i][0], al[i][1], al[i][2], al[i][3], sb + SM_ALO + off);
            }
            #pragma unroll
            for (int jj = 0; jj < 2; jj++) {
                int n = nw * 32 + jj * 16 + ((lane >> 4) << 3) + (lane & 7);
                int k = kcc + (((lane >> 3) & 1) << 3);
                uint32_t off = (uint32_t)(n * GP + k * 2);
                ldsm4(bh_[jj*2][0], bh_[jj*2][1], bh_[jj*2+1][0], bh_[jj*2+1][1], sb + SM_BHI + off);
                ldsm4(bl_[jj*2][0], bl_[jj*2][1], bl_[jj*2+1][0], bl_[jj*2+1][1], sb + SM_BLO + off);
            }
            #pragma unroll
            for (int i = 0; i < 2; i++)
                #pragma unroll
                for (int j = 0; j < 4; j++) {
                    mma16816(acc[i][j], ah[i], bh_[j]);
                    mma16816(acc[i][j], ah[i], bl_[j]);
                    mma16816(acc[i][j], al[i], bh_[j]);
                }
        }
        __syncthreads();
    }

    // Epilogue: vec fp32
    const int gid = lane >> 2, tg = lane & 3;
    #pragma unroll
    for (int i = 0; i < 2; i++)
        #pragma unroll
        for (int j = 0; j < 4; j++) {
            int c = nw * 32 + j * 8 + tg * 2;
            #pragma unroll
            for (int eh = 0; eh < 2; eh++) {
                int q = q0 + mw * 32 + i * 16 + gid + 8 * eh;
                *reinterpret_cast<float2*>(
                    g_vec + (size_t)(b3 * QLL + q) * HDD + h3 * DD + c) =
                    make_float2(acc[i][j][eh * 2 + 0], acc[i][j][eh * 2 + 1]);
            }
        }
}

// ---------------------------------------------------------------------------
// Launch
// ---------------------------------------------------------------------------
extern "C" void kernel_launch(void* const* d_in, const int* in_sizes, int n_in,
                              void* d_out, int out_size)
{
    (void)in_sizes; (void)n_in; (void)out_size;

    const float*  Q    = (const float*)d_in[0];
    const float*  Kin  = (const float*)d_in[1];
    const float*  Vin  = (const float*)d_in[2];
    const float*  pos  = (const float*)d_in[3];
    const float*  rwb  = (const float*)d_in[4];
    const float*  rrb  = (const float*)d_in[5];
    const mask_t* mask = (const mask_t*)d_in[6];
    // d_in[7] = mems (unused)
    const float*  Wq = (const float*)d_in[8];
    const float*  bq = (const float*)d_in[9];
    const float*  Wk = (const float*)d_in[10];
    const float*  bk = (const float*)d_in[11];
    const float*  Wv = (const float*)d_in[12];
    const float*  bv = (const float*)d_in[13];
    const float*  Wr = (const float*)d_in[14];
    const float*  Wo = (const float*)d_in[15];
    const float*  bo = (const float*)d_in[16];

    float* out  = (float*)d_out;
    float* prob = out + (size_t)BB * QLL * EE;

    u16 *qwh, *qwl, *qrh, *qrl, *kh, *kl, *vh, *vl, *rh, *rl;
    float *pvec;
    cudaGetSymbolAddress((void**)&qwh, g_qw_h);
    cudaGetSymbolAddress((void**)&qwl, g_qw_l);
    cudaGetSymbolAddress((void**)&qrh, g_qr_h);
    cudaGetSymbolAddress((void**)&qrl, g_qr_l);
    cudaGetSymbolAddress((void**)&kh,  g_k_h);
    cudaGetSymbolAddress((void**)&kl,  g_k_l);
    cudaGetSymbolAddress((void**)&vh,  g_v_h);
    cudaGetSymbolAddress((void**)&vl,  g_v_l);
    cudaGetSymbolAddress((void**)&rh,  g_r_h);
    cudaGetSymbolAddress((void**)&rl,  g_r_l);
    cudaGetSymbolAddress((void**)&pvec, g_vec);

    cudaFuncSetAttribute(tgemm,  cudaFuncAttributeMaxDynamicSharedMemorySize, SM_G_TOTAL);
    cudaFuncSetAttribute(tscore, cudaFuncAttributeMaxDynamicSharedMemorySize, SS_TOTAL);
    cudaFuncSetAttribute(probpv, cudaFuncAttributeMaxDynamicSharedMemorySize, PP_TOTAL);

    const dim3 blk(256);

    // Q projection -> qw/qr bf16 pairs (bias + r_w_bias / r_r_bias folded)
    tgemm<<<dim3(HDD / 64, (BB * QLL) / 128, 1), blk, SM_G_TOTAL>>>(
        Q,   EE, 0, 0,  Wq, HDD, 0, 0,  bq, 2,
        nullptr, qwh, qwl, qrh, qrl, rwb, rrb,
        HDD, 0, 0, EE, 1);
    // K projection -> bf16
    tgemm<<<dim3(HDD / 64, (BB * KLL) / 128, 1), blk, SM_G_TOTAL>>>(
        Kin, EE, 0, 0,  Wk, HDD, 0, 0,  bk, 1,
        nullptr, kh, kl, nullptr, nullptr, nullptr, nullptr,
        HDD, 0, 0, EE, 1);
    // V projection -> bf16
    tgemm<<<dim3(HDD / 64, (BB * KLL) / 128, 1), blk, SM_G_TOTAL>>>(
        Vin, EE, 0, 0,  Wv, HDD, 0, 0,  bv, 1,
        nullptr, vh, vl, nullptr, nullptr, nullptr, nullptr,
        HDD, 0, 0, EE, 1);
    // r projection -> bf16 (no bias)
    tgemm<<<dim3(HDD / 64, KLL / 128, 1), blk, SM_G_TOTAL>>>(
        pos, EE, 0, 0,  Wr, HDD, 0, 0,  nullptr, 1,
        nullptr, rh, rl, nullptr, nullptr, nullptr, nullptr,
        HDD, 0, 0, EE, 1);

    // Scores + online softmax stats
    tscore<<<dim3(1, QLL / 128, BB * HH), blk, SS_TOTAL>>>(mask);

    // prob + PV fused
    probpv<<<dim3(1, QLL / 128, BB * HH), blk, PP_TOTAL>>>(prob);

    // Output projection (fp32 path)
    tgemm<<<dim3(EE / 64, (BB * QLL) / 128, 1), blk, SM_G_TOTAL>>>(
        pvec, HDD, 0, 0,  Wo, EE, 0, 0,  bo, 0,
        out, nullptr, nullptr, nullptr, nullptr, nullptr, nullptr,
        EE, 0, 0, HDD, 1);
}

// round 6
// speedup vs baseline: 1.3256x; 1.3256x over previous
#include <cuda_runtime.h>
#include <cuda_bf16.h>
#include <stdint.h>

// ---------------------------------------------------------------------------
// Problem constants
// ---------------------------------------------------------------------------
#define BB   2
#define HH   12
#define DD   64
#define EE   768
#define QLL  1024
#define KLL  2048
#define HDD  768
#define SCALEF 0.125f
typedef int mask_t;   // harness widens bool -> int32
typedef unsigned short u16;

// ---------------------------------------------------------------------------
// Scratch (device globals)
// ---------------------------------------------------------------------------
// converted inputs: Q(2048 rows), K(4096), V(4096), pos(2048) x 768, bf16 hi/lo
#define XQ 0
#define XK ((size_t)2048 * 768)
#define XV ((size_t)6144 * 768)
#define XR ((size_t)10240 * 768)
__device__ u16 g_x_h[(size_t)12288 * 768];
__device__ u16 g_x_l[(size_t)12288 * 768];
// converted+transposed weights: [n][k] each 768x768
#define WQO ((size_t)0)
#define WKO ((size_t)1 * 768 * 768)
#define WVO ((size_t)2 * 768 * 768)
#define WRO ((size_t)3 * 768 * 768)
#define WOO ((size_t)4 * 768 * 768)
__device__ u16 g_w_h[(size_t)5 * 768 * 768];
__device__ u16 g_w_l[(size_t)5 * 768 * 768];
// projected operands (bf16 hi/lo)
__device__ u16 g_qw_h[(size_t)BB * QLL * HDD];
__device__ u16 g_qw_l[(size_t)BB * QLL * HDD];
__device__ u16 g_qr_h[(size_t)BB * QLL * HDD];
__device__ u16 g_qr_l[(size_t)BB * QLL * HDD];
__device__ u16 g_k_h [(size_t)BB * KLL * HDD];
__device__ u16 g_k_l [(size_t)BB * KLL * HDD];
__device__ u16 g_v_h [(size_t)BB * KLL * HDD];
__device__ u16 g_v_l [(size_t)BB * KLL * HDD];
__device__ u16 g_r_h [(size_t)KLL * HDD];
__device__ u16 g_r_l [(size_t)KLL * HDD];
__device__ u16 g_vec_h[(size_t)BB * QLL * HDD];
__device__ u16 g_vec_l[(size_t)BB * QLL * HDD];
__device__ float g_s[(size_t)BB * HH * QLL * KLL];

// ---------------------------------------------------------------------------
// Primitives
// ---------------------------------------------------------------------------
__device__ __forceinline__ uint32_t smem_u32(const void* p) {
    uint32_t a;
    asm("{ .reg .u64 t; cvta.to.shared.u64 t, %1; cvt.u32.u64 %0, t; }" : "=r"(a) : "l"(p));
    return a;
}
__device__ __forceinline__ void ldsm4(uint32_t& r0, uint32_t& r1, uint32_t& r2, uint32_t& r3,
                                      uint32_t a) {
    asm volatile("ldmatrix.sync.aligned.m8n8.x4.shared.b16 {%0,%1,%2,%3}, [%4];"
                 : "=r"(r0), "=r"(r1), "=r"(r2), "=r"(r3) : "r"(a));
}
__device__ __forceinline__ void mma16816(float* c, const uint32_t* a, const uint32_t* b) {
    asm volatile("mma.sync.aligned.m16n8k16.row.col.f32.bf16.bf16.f32 "
                 "{%0,%1,%2,%3}, {%4,%5,%6,%7}, {%8,%9}, {%0,%1,%2,%3};"
                 : "+f"(c[0]), "+f"(c[1]), "+f"(c[2]), "+f"(c[3])
                 : "r"(a[0]), "r"(a[1]), "r"(a[2]), "r"(a[3]), "r"(b[0]), "r"(b[1]));
}
__device__ __forceinline__ void cpa16(uint32_t dst, const void* src) {
    asm volatile("cp.async.cg.shared.global [%0], [%1], 16;" :: "r"(dst), "l"(src));
}
#define CP_COMMIT() asm volatile("cp.async.commit_group;" ::: "memory")
#define CP_WAIT(n)  asm volatile("cp.async.wait_group %0;" :: "n"(n) : "memory")

__device__ __forceinline__ void split_bf16(float x, u16& h, u16& l) {
    __nv_bfloat16 hb = __float2bfloat16(x);
    h = __bfloat16_as_ushort(hb);
    l = __bfloat16_as_ushort(__float2bfloat16(x - __bfloat162float(hb)));
}
__device__ __forceinline__ void split4(float4 v, uint2& hi, uint2& lo) {
    u16 h0, h1, h2, h3, l0, l1, l2, l3;
    split_bf16(v.x, h0, l0); split_bf16(v.y, h1, l1);
    split_bf16(v.z, h2, l2); split_bf16(v.w, h3, l3);
    hi = make_uint2((uint32_t)h0 | ((uint32_t)h1 << 16), (uint32_t)h2 | ((uint32_t)h3 << 16));
    lo = make_uint2((uint32_t)l0 | ((uint32_t)l1 << 16), (uint32_t)l2 | ((uint32_t)l3 << 16));
}

// Warp-tile MMA step (32x32 per warp, k16), 3-pass hi/lo; P = smem row pitch.
template<int P>
__device__ __forceinline__ void warp_mma(uint32_t sb, uint32_t aHi, uint32_t aLo,
                                         uint32_t bHi, uint32_t bLo,
                                         int kcc, int mw, int nw, int lane,
                                         float acc[2][4][4])
{
    uint32_t ah[2][4], al[2][4], bh[4][2], bl[4][2];
    #pragma unroll
    for (int i = 0; i < 2; i++) {
        int row = mw * 32 + i * 16 + (lane & 15);
        int col = kcc + ((lane >> 4) << 3);
        uint32_t off = (uint32_t)(row * P + col * 2);
        ldsm4(ah[i][0], ah[i][1], ah[i][2], ah[i][3], sb + aHi + off);
        ldsm4(al[i][0], al[i][1], al[i][2], al[i][3], sb + aLo + off);
    }
    #pragma unroll
    for (int jj = 0; jj < 2; jj++) {
        int n = nw * 32 + jj * 16 + ((lane >> 4) << 3) + (lane & 7);
        int k = kcc + (((lane >> 3) & 1) << 3);
        uint32_t off = (uint32_t)(n * P + k * 2);
        ldsm4(bh[jj*2][0], bh[jj*2][1], bh[jj*2+1][0], bh[jj*2+1][1], sb + bHi + off);
        ldsm4(bl[jj*2][0], bl[jj*2][1], bl[jj*2+1][0], bl[jj*2+1][1], sb + bLo + off);
    }
    #pragma unroll
    for (int i = 0; i < 2; i++)
        #pragma unroll
        for (int j = 0; j < 4; j++) {
            mma16816(acc[i][j], ah[i], bh[j]);
            mma16816(acc[i][j], ah[i], bl[j]);
            mma16816(acc[i][j], al[i], bh[j]);
        }
}

// ---------------------------------------------------------------------------
// Convert kernels
// ---------------------------------------------------------------------------
__global__ void cvt(const float* __restrict__ s, u16* __restrict__ dh,
                    u16* __restrict__ dl, int n)
{
    int i = (blockIdx.x * blockDim.x + threadIdx.x) * 4;
    if (i >= n) return;
    float4 v = *reinterpret_cast<const float4*>(s + i);
    uint2 h, l; split4(v, h, l);
    *reinterpret_cast<uint2*>(dh + i) = h;
    *reinterpret_cast<uint2*>(dl + i) = l;
}

// transpose 768x768: out[n][k] = W[k][n], split bf16
__global__ void cvtT(const float* __restrict__ W, u16* __restrict__ th,
                     u16* __restrict__ tl)
{
    __shared__ float t[32][33];
    const int nb = blockIdx.x * 32, kb = blockIdx.y * 32;
    const int tx = threadIdx.x, ty = threadIdx.y;
    #pragma unroll
    for (int i = 0; i < 4; i++)
        t[ty + i * 8][tx] = W[(size_t)(kb + ty + i * 8) * 768 + nb + tx];
    __syncthreads();
    #pragma unroll
    for (int i = 0; i < 4; i++) {
        float v = t[tx][ty + i * 8];
        u16 h, l; split_bf16(v, h, l);
        size_t o = (size_t)(nb + ty + i * 8) * 768 + kb + tx;
        th[o] = h; tl[o] = l;
    }
}

// ---------------------------------------------------------------------------
// tgemm (pure bf16, cp.async double-buffered):
//   C[M,N] = A[M,K] * B^T + bias; A (hi/lo) [M][K] k-contig; B (hi/lo) [N][K].
//   Block tile 128x64, K-slab 64, 8 warps (4m x 2n).
//   mode 0: Cf fp32;  mode 1: split->C1;  mode 2: split(v+add1)->C1, split(v+add2)->C2.
// ---------------------------------------------------------------------------
#define GP 144
#define TG_AHI 0
#define TG_ALO (128 * GP)
#define TG_BHI (2 * 128 * GP)
#define TG_BLO (2 * 128 * GP + 64 * GP)
#define TG_STAGE (2 * 128 * GP + 2 * 64 * GP)   // 55296
#define TG_TOTAL (2 * TG_STAGE)                 // 110592

__global__ void __launch_bounds__(256, 2)
tgemm(const u16* __restrict__ Ah, const u16* __restrict__ Al, long lda,
      const u16* __restrict__ Bh, const u16* __restrict__ Bl, long ldb,
      const float* __restrict__ bias, int mode,
      float* __restrict__ Cf, u16* __restrict__ C1h, u16* __restrict__ C1l,
      u16* __restrict__ C2h, u16* __restrict__ C2l,
      const float* __restrict__ add1, const float* __restrict__ add2,
      long ldc, int K)
{
    extern __shared__ char sm[];
    const uint32_t sb = smem_u32(sm);
    const int tid = threadIdx.x, wid = tid >> 5, lane = tid & 31;
    const int mw = wid >> 1, nw = wid & 1;
    const int m0 = blockIdx.y << 7;
    const int n0 = blockIdx.x << 6;
    const int nslab = K >> 6;

    auto issue = [&](int s, int st) {
        const uint32_t base = sb + st * TG_STAGE;
        const int k0 = s << 6;
        // A: 128 rows x 8 chunks, hi+lo
        #pragma unroll
        for (int it = 0; it < 4; it++) {
            int id = it * 256 + tid;
            int m = id >> 3, c = id & 7;
            size_t src = (size_t)(m0 + m) * lda + k0 + c * 8;
            uint32_t dst = base + TG_AHI + m * GP + c * 16;
            cpa16(dst, Ah + src);
            cpa16(dst + (TG_ALO - TG_AHI), Al + src);
        }
        // B: 64 rows x 8 chunks, hi+lo
        #pragma unroll
        for (int it = 0; it < 2; it++) {
            int id = it * 256 + tid;
            int n = id >> 3, c = id & 7;
            size_t src = (size_t)(n0 + n) * ldb + k0 + c * 8;
            uint32_t dst = base + TG_BHI + n * GP + c * 16;
            cpa16(dst, Bh + src);
            cpa16(dst + (TG_BLO - TG_BHI), Bl + src);
        }
    };

    issue(0, 0); CP_COMMIT();

    float acc[2][4][4] = {};
    for (int s = 0; s < nslab; s++) {
        if (s + 1 < nslab) { issue(s + 1, (s + 1) & 1); CP_COMMIT(); CP_WAIT(1); }
        else               { CP_WAIT(0); }
        __syncthreads();
        const uint32_t st = (uint32_t)((s & 1) * TG_STAGE);
        #pragma unroll
        for (int ks = 0; ks < 4; ks++)
            warp_mma<GP>(sb, st + TG_AHI, st + TG_ALO, st + TG_BHI, st + TG_BLO,
                         ks << 4, mw, nw, lane, acc);
        __syncthreads();
    }

    // Epilogue
    const int gid = lane >> 2, tg = lane & 3;
    #pragma unroll
    for (int i = 0; i < 2; i++)
        #pragma unroll
        for (int j = 0; j < 4; j++) {
            int c = n0 + nw * 32 + j * 8 + tg * 2;
            float b0 = bias ? bias[c] : 0.f;
            float b1 = bias ? bias[c + 1] : 0.f;
            #pragma unroll
            for (int eh = 0; eh < 2; eh++) {
                int r = m0 + mw * 32 + i * 16 + gid + 8 * eh;
                size_t base = (size_t)r * ldc + c;
                float v0 = acc[i][j][eh * 2 + 0] + b0;
                float v1 = acc[i][j][eh * 2 + 1] + b1;
                if (mode == 0) {
                    *reinterpret_cast<float2*>(Cf + base) = make_float2(v0, v1);
                } else if (mode == 1) {
                    u16 h0, l0, h1, l1;
                    split_bf16(v0, h0, l0); split_bf16(v1, h1, l1);
                    *reinterpret_cast<uint32_t*>(C1h + base) = (uint32_t)h0 | ((uint32_t)h1 << 16);
                    *reinterpret_cast<uint32_t*>(C1l + base) = (uint32_t)l0 | ((uint32_t)l1 << 16);
                } else {
                    u16 h0, l0, h1, l1;
                    split_bf16(v0 + add1[c], h0, l0); split_bf16(v1 + add1[c + 1], h1, l1);
                    *reinterpret_cast<uint32_t*>(C1h + base) = (uint32_t)h0 | ((uint32_t)h1 << 16);
                    *reinterpret_cast<uint32_t*>(C1l + base) = (uint32_t)l0 | ((uint32_t)l1 << 16);
                    split_bf16(v0 + add2[c], h0, l0); split_bf16(v1 + add2[c + 1], h1, l1);
                    *reinterpret_cast<uint32_t*>(C2h + base) = (uint32_t)h0 | ((uint32_t)h1 << 16);
                    *reinterpret_cast<uint32_t*>(C2l + base) = (uint32_t)l0 | ((uint32_t)l1 << 16);
                }
            }
        }
}

// ---------------------------------------------------------------------------
// tscore: S = mask ? -1e9 : (A' * B'^T)*SCALE -> g_s
// A'[m,0:64]=qw(b3,h3), A'[m,64:128]=qr(bu,hm1) (or 0); resident in smem.
// B'[n,0:64]=k(b3,h3),  B'[n,64:128]=r(hm1)     (or 0); cp.async double-buffer.
// ---------------------------------------------------------------------------
#define SP 272
#define TS_AHI 0
#define TS_ALO (128 * SP)                 // 34816
#define TS_B   (2 * 128 * SP)             // 69632
#define TS_BSTG (2 * 64 * SP)             // 34816 per stage (hi+lo)
#define TS_BLOD (64 * SP)                 // 17408 lo offset within stage
#define TS_TOTAL (TS_B + 2 * TS_BSTG)     // 139264

__global__ void __launch_bounds__(256)
tscore(const mask_t* __restrict__ mask)
{
    extern __shared__ char sm[];
    const uint32_t sb = smem_u32(sm);
    const int tid = threadIdx.x, wid = tid >> 5, lane = tid & 31;
    const int mw = wid >> 1, nw = wid & 1;
    const int gid = lane >> 2, tg = lane & 3;
    const int bh = blockIdx.z;
    const int b3 = bh / HH, h3 = bh % HH;
    const int mp = bh + BB;
    const int bu = mp / (HH + 1), hh = mp % (HH + 1);
    const int has_bd = (hh != 0);
    const int hm1 = hh - 1;
    const int q0 = blockIdx.y << 7;

    // A' fill (plain 16B loads, once)
    #pragma unroll
    for (int it = 0; it < 8; it++) {
        int id = it * 256 + tid;           // 0..2047
        int m = id >> 4, c = id & 15;
        uint4 hv, lv;
        if (c < 8) {
            size_t src = (size_t)(b3 * QLL + q0 + m) * HDD + h3 * DD + c * 8;
            hv = *reinterpret_cast<const uint4*>(g_qw_h + src);
            lv = *reinterpret_cast<const uint4*>(g_qw_l + src);
        } else if (has_bd) {
            size_t src = (size_t)(bu * QLL + q0 + m) * HDD + hm1 * DD + (c - 8) * 8;
            hv = *reinterpret_cast<const uint4*>(g_qr_h + src);
            lv = *reinterpret_cast<const uint4*>(g_qr_l + src);
        } else {
            hv = make_uint4(0u, 0u, 0u, 0u); lv = hv;
        }
        int off = m * SP + c * 16;
        *reinterpret_cast<uint4*>(sm + TS_AHI + off) = hv;
        *reinterpret_cast<uint4*>(sm + TS_ALO + off) = lv;
    }
    // Zero B' second halves if no BD term (they are never cp.async'd then)
    if (!has_bd) {
        uint4 z = make_uint4(0u, 0u, 0u, 0u);
        for (int id = tid; id < 64 * 8; id += 256) {
            int n = id >> 3, c = id & 7;
            int o = TS_B + n * SP + 128 + c * 16;
            *reinterpret_cast<uint4*>(sm + o) = z;
            *reinterpret_cast<uint4*>(sm + o + TS_BLOD) = z;
            *reinterpret_cast<uint4*>(sm + o + TS_BSTG) = z;
            *reinterpret_cast<uint4*>(sm + o + TS_BSTG + TS_BLOD) = z;
        }
    }

    auto issueB = [&](int kt, int st) {
        const uint32_t base = sb + TS_B + st * TS_BSTG;
        const int kc = kt << 6;
        const int nch = has_bd ? 16 : 8;
        const int tot = 64 * nch;
        for (int id = tid; id < tot; id += 256) {
            int n = id / nch, c = id % nch;
            uint32_t dst = base + n * SP + c * 16;
            if (c < 8) {
                size_t src = (size_t)(b3 * KLL + kc + n) * HDD + h3 * DD + c * 8;
                cpa16(dst, g_k_h + src);
                cpa16(dst + TS_BLOD, g_k_l + src);
            } else {
                size_t src = (size_t)(kc + n) * HDD + hm1 * DD + (c - 8) * 8;
                cpa16(dst, g_r_h + src);
                cpa16(dst + TS_BLOD, g_r_l + src);
            }
        }
    };

    issueB(0, 0); CP_COMMIT();

    for (int kt = 0; kt < 32; kt++) {
        if (kt + 1 < 32) { issueB(kt + 1, (kt + 1) & 1); CP_COMMIT(); CP_WAIT(1); }
        else             { CP_WAIT(0); }
        __syncthreads();

        float acc[2][4][4] = {};
        const uint32_t bst = (uint32_t)(TS_B + (kt & 1) * TS_BSTG);
        #pragma unroll
        for (int ks = 0; ks < 8; ks++)
            warp_mma<SP>(sb, TS_AHI, TS_ALO, bst, bst + TS_BLOD,
                         ks << 4, mw, nw, lane, acc);

        // Epilogue: mask + scale -> g_s
        const int kc = kt << 6;
        #pragma unroll
        for (int i = 0; i < 2; i++)
            #pragma unroll
            for (int j = 0; j < 4; j++) {
                int q = q0 + mw * 32 + i * 16 + gid;
                int c = kc + nw * 32 + j * 8 + tg * 2;
                const size_t mrow0 = (size_t)(b3 * QLL + q) * KLL + c;
                const size_t srow0 = ((size_t)bh * QLL + q) * KLL + c;
                int2 mk = *reinterpret_cast<const int2*>(mask + mrow0);
                *reinterpret_cast<float2*>(g_s + srow0) = make_float2(
                    mk.x ? -1e9f : acc[i][j][0] * SCALEF,
                    mk.y ? -1e9f : acc[i][j][1] * SCALEF);
                mk = *reinterpret_cast<const int2*>(mask + mrow0 + 8 * KLL);
                *reinterpret_cast<float2*>(g_s + srow0 + 8 * KLL) = make_float2(
                    mk.x ? -1e9f : acc[i][j][2] * SCALEF,
                    mk.y ? -1e9f : acc[i][j][3] * SCALEF);
            }
        __syncthreads();
    }
}

// ---------------------------------------------------------------------------
// Softmax: one block per (b,h,q) row of 2048; registers-resident.
// ---------------------------------------------------------------------------
__device__ __forceinline__ float warp_max(float v) {
    #pragma unroll
    for (int o = 16; o; o >>= 1) v = fmaxf(v, __shfl_xor_sync(0xffffffffu, v, o));
    return v;
}
__device__ __forceinline__ float warp_sum(float v) {
    #pragma unroll
    for (int o = 16; o; o >>= 1) v += __shfl_xor_sync(0xffffffffu, v, o);
    return v;
}

__global__ __launch_bounds__(256)
void softmax_kernel(const float* __restrict__ S, float* __restrict__ P)
{
    const size_t row = blockIdx.x;
    const float* s = S + row * KLL;
    float*       p = P + row * KLL;

    __shared__ float sh[8];
    const int wid = threadIdx.x >> 5;
    const int lid = threadIdx.x & 31;

    float v[8];
    float m = -3.0e38f;
    #pragma unroll
    for (int i = 0; i < 8; i++) {
        v[i] = s[threadIdx.x + i * 256];
        m = fmaxf(m, v[i]);
    }
    float wm = warp_max(m);
    if (lid == 0) sh[wid] = wm;
    __syncthreads();
    if (wid == 0) {
        float t = (lid < 8) ? sh[lid] : -3.0e38f;
        t = warp_max(t);
        if (lid == 0) sh[0] = t;
    }
    __syncthreads();
    const float bm = sh[0];

    float lsum = 0.0f;
    #pragma unroll
    for (int i = 0; i < 8; i++) {
        v[i] = __expf(v[i] - bm);
        lsum += v[i];
    }
    float ws = warp_sum(lsum);
    __syncthreads();
    if (lid == 0) sh[wid] = ws;
    __syncthreads();
    if (wid == 0) {
        float t = (lid < 8) ? sh[lid] : 0.0f;
        t = warp_sum(t);
        if (lid == 0) sh[0] = t;
    }
    __syncthreads();
    const float inv = 1.0f / sh[0];

    #pragma unroll
    for (int i = 0; i < 8; i++)
        p[threadIdx.x + i * 256] = v[i] * inv;
}

// ---------------------------------------------------------------------------
// pv: vec = prob @ V_h ; prob fp32 split in-kernel, V bf16 precomputed.
// Epilogue writes vec as bf16 hi/lo for the output projection.
// ---------------------------------------------------------------------------
__global__ void __launch_bounds__(256, 2)
pv_kernel(const float* __restrict__ prob)
{
    extern __shared__ char sm[];
    const uint32_t sb = smem_u32(sm);
    const int tid = threadIdx.x, wid = tid >> 5, lane = tid & 31;
    const int mw = wid >> 1, nw = wid & 1;
    const int bh = blockIdx.z;
    const int b3 = bh / HH, h3 = bh % HH;
    const int q0 = blockIdx.y << 7;

    float acc[2][4][4] = {};

    for (int kt = 0; kt < 32; kt++) {
        const int kc = kt << 6;
        #pragma unroll
        for (int it = 0; it < 8; it++) {
            int idx = (it * 256 + tid) << 2;
            int m = idx >> 6, k = idx & 63;
            float4 p4 = *reinterpret_cast<const float4*>(
                prob + ((size_t)bh * QLL + q0 + m) * KLL + kc + k);
            uint2 hi, lo; split4(p4, hi, lo);
            int off = m * GP + k * 2;
            *reinterpret_cast<uint2*>(sm + TG_AHI + off) = hi;
            *reinterpret_cast<uint2*>(sm + TG_ALO + off) = lo;
        }
        #pragma unroll
        for (int it = 0; it < 16; it++) {
            int idx = it * 256 + tid;
            int k = idx >> 6, n = idx & 63;
            size_t base = (size_t)(b3 * KLL + kc + k) * HDD + h3 * DD + n;
            int off = n * GP + k * 2;
            *reinterpret_cast<u16*>(sm + TG_BHI + off) = g_v_h[base];
            *reinterpret_cast<u16*>(sm + TG_BLO + off) = g_v_l[base];
        }
        __syncthreads();
        #pragma unroll
        for (int ks = 0; ks < 4; ks++)
            warp_mma<GP>(sb, TG_AHI, TG_ALO, TG_BHI, TG_BLO, ks << 4, mw, nw, lane, acc);
        __syncthreads();
    }

    const int gid = lane >> 2, tg = lane & 3;
    #pragma unroll
    for (int i = 0; i < 2; i++)
        #pragma unroll
        for (int j = 0; j < 4; j++) {
            int c = nw * 32 + j * 8 + tg * 2;
            #pragma unroll
            for (int eh = 0; eh < 2; eh++) {
                int q = q0 + mw * 32 + i * 16 + gid + 8 * eh;
                size_t base = (size_t)(b3 * QLL + q) * HDD + h3 * DD + c;
                u16 h0, l0, h1, l1;
                split_bf16(acc[i][j][eh * 2 + 0], h0, l0);
                split_bf16(acc[i][j][eh * 2 + 1], h1, l1);
                *reinterpret_cast<uint32_t*>(g_vec_h + base) = (uint32_t)h0 | ((uint32_t)h1 << 16);
                *reinterpret_cast<uint32_t*>(g_vec_l + base) = (uint32_t)l0 | ((uint32_t)l1 << 16);
            }
        }
}

// ---------------------------------------------------------------------------
// Launch
// ---------------------------------------------------------------------------
extern "C" void kernel_launch(void* const* d_in, const int* in_sizes, int n_in,
                              void* d_out, int out_size)
{
    (void)in_sizes; (void)n_in; (void)out_size;

    const float*  Q    = (const float*)d_in[0];
    const float*  Kin  = (const float*)d_in[1];
    const float*  Vin  = (const float*)d_in[2];
    const float*  pos  = (const float*)d_in[3];
    const float*  rwb  = (const float*)d_in[4];
    const float*  rrb  = (const float*)d_in[5];
    const mask_t* mask = (const mask_t*)d_in[6];
    // d_in[7] = mems (unused)
    const float*  Wq = (const float*)d_in[8];
    const float*  bq = (const float*)d_in[9];
    const float*  Wk = (const float*)d_in[10];
    const float*  bk = (const float*)d_in[11];
    const float*  Wv = (const float*)d_in[12];
    const float*  bv = (const float*)d_in[13];
    const float*  Wr = (const float*)d_in[14];
    const float*  Wo = (const float*)d_in[15];
    const float*  bo = (const float*)d_in[16];

    float* out  = (float*)d_out;
    float* prob = out + (size_t)BB * QLL * EE;

    u16 *xh, *xl, *wh, *wl;
    u16 *qwh, *qwl, *qrh, *qrl, *kh, *kl, *vh, *vl, *rh, *rl, *vech, *vecl;
    float *ps;
    cudaGetSymbolAddress((void**)&xh, g_x_h);
    cudaGetSymbolAddress((void**)&xl, g_x_l);
    cudaGetSymbolAddress((void**)&wh, g_w_h);
    cudaGetSymbolAddress((void**)&wl, g_w_l);
    cudaGetSymbolAddress((void**)&qwh, g_qw_h);
    cudaGetSymbolAddress((void**)&qwl, g_qw_l);
    cudaGetSymbolAddress((void**)&qrh, g_qr_h);
    cudaGetSymbolAddress((void**)&qrl, g_qr_l);
    cudaGetSymbolAddress((void**)&kh,  g_k_h);
    cudaGetSymbolAddress((void**)&kl,  g_k_l);
    cudaGetSymbolAddress((void**)&vh,  g_v_h);
    cudaGetSymbolAddress((void**)&vl,  g_v_l);
    cudaGetSymbolAddress((void**)&rh,  g_r_h);
    cudaGetSymbolAddress((void**)&rl,  g_r_l);
    cudaGetSymbolAddress((void**)&vech, g_vec_h);
    cudaGetSymbolAddress((void**)&vecl, g_vec_l);
    cudaGetSymbolAddress((void**)&ps,  g_s);

    cudaFuncSetAttribute(tgemm,     cudaFuncAttributeMaxDynamicSharedMemorySize, TG_TOTAL);
    cudaFuncSetAttribute(tscore,    cudaFuncAttributeMaxDynamicSharedMemorySize, TS_TOTAL);
    cudaFuncSetAttribute(pv_kernel, cudaFuncAttributeMaxDynamicSharedMemorySize, TG_STAGE);

    const dim3 blk(256);

    // Converts
    cvt<<<(2048 * 768) / 1024, blk>>>(Q,   xh + XQ, xl + XQ, 2048 * 768);
    cvt<<<(4096 * 768) / 1024, blk>>>(Kin, xh + XK, xl + XK, 4096 * 768);
    cvt<<<(4096 * 768) / 1024, blk>>>(Vin, xh + XV, xl + XV, 4096 * 768);
    cvt<<<(2048 * 768) / 1024, blk>>>(pos, xh + XR, xl + XR, 2048 * 768);
    dim3 tgrid(24, 24), tblk(32, 8);
    cvtT<<<tgrid, tblk>>>(Wq, wh + WQO, wl + WQO);
    cvtT<<<tgrid, tblk>>>(Wk, wh + WKO, wl + WKO);
    cvtT<<<tgrid, tblk>>>(Wv, wh + WVO, wl + WVO);
    cvtT<<<tgrid, tblk>>>(Wr, wh + WRO, wl + WRO);
    cvtT<<<tgrid, tblk>>>(Wo, wh + WOO, wl + WOO);

    // Projections
    tgemm<<<dim3(12, 16), blk, TG_TOTAL>>>(
        xh + XQ, xl + XQ, EE, wh + WQO, wl + WQO, EE, bq, 2,
        nullptr, qwh, qwl, qrh, qrl, rwb, rrb, HDD, EE);
    tgemm<<<dim3(12, 32), blk, TG_TOTAL>>>(
        xh + XK, xl + XK, EE, wh + WKO, wl + WKO, EE, bk, 1,
        nullptr, kh, kl, nullptr, nullptr, nullptr, nullptr, HDD, EE);
    tgemm<<<dim3(12, 32), blk, TG_TOTAL>>>(
        xh + XV, xl + XV, EE, wh + WVO, wl + WVO, EE, bv, 1,
        nullptr, vh, vl, nullptr, nullptr, nullptr, nullptr, HDD, EE);
    tgemm<<<dim3(12, 16), blk, TG_TOTAL>>>(
        xh + XR, xl + XR, EE, wh + WRO, wl + WRO, EE, nullptr, 1,
        nullptr, rh, rl, nullptr, nullptr, nullptr, nullptr, HDD, EE);

    // Scores
    tscore<<<dim3(1, QLL / 128, BB * HH), blk, TS_TOTAL>>>(mask);

    // Softmax -> prob
    softmax_kernel<<<BB * HH * QLL, blk>>>(ps, prob);

    // PV
    pv_kernel<<<dim3(1, QLL / 128, BB * HH), blk, TG_STAGE>>>(prob);

    // Output projection
    tgemm<<<dim3(12, 16), blk, TG_TOTAL>>>(
        vech, vecl, HDD, wh + WOO, wl + WOO, HDD, bo, 0,
        out, nullptr, nullptr, nullptr, nullptr, nullptr, nullptr, EE, HDD);
}

// round 7
// speedup vs baseline: 1.4130x; 1.0659x over previous
#include <cuda_runtime.h>
#include <cuda_bf16.h>
#include <stdint.h>

// ---------------------------------------------------------------------------
// Problem constants
// ---------------------------------------------------------------------------
#define BB   2
#define HH   12
#define DD   64
#define EE   768
#define QLL  1024
#define KLL  2048
#define HDD  768
#define SCALEF 0.125f
typedef int mask_t;   // harness widens bool -> int32
typedef unsigned short u16;
typedef unsigned char u8;

// ---------------------------------------------------------------------------
// Scratch (device globals)
// ---------------------------------------------------------------------------
#define XQ 0
#define XK ((size_t)2048 * 768)
#define XV ((size_t)6144 * 768)
#define XR ((size_t)10240 * 768)
__device__ u16 g_x_h[(size_t)12288 * 768];
__device__ u16 g_x_l[(size_t)12288 * 768];
#define WQO ((size_t)0)
#define WKO ((size_t)1 * 768 * 768)
#define WVO ((size_t)2 * 768 * 768)
#define WRO ((size_t)3 * 768 * 768)
#define WOO ((size_t)4 * 768 * 768)
__device__ u16 g_w_h[(size_t)5 * 768 * 768];
__device__ u16 g_w_l[(size_t)5 * 768 * 768];
__device__ u16 g_qw_h[(size_t)BB * QLL * HDD];
__device__ u16 g_qw_l[(size_t)BB * QLL * HDD];
__device__ u16 g_qr_h[(size_t)BB * QLL * HDD];
__device__ u16 g_qr_l[(size_t)BB * QLL * HDD];
__device__ u16 g_k_h [(size_t)BB * KLL * HDD];
__device__ u16 g_k_l [(size_t)BB * KLL * HDD];
__device__ u16 g_v_h [(size_t)BB * KLL * HDD];
__device__ u16 g_v_l [(size_t)BB * KLL * HDD];
__device__ u16 g_r_h [(size_t)KLL * HDD];
__device__ u16 g_r_l [(size_t)KLL * HDD];
__device__ u16 g_vec_h[(size_t)BB * QLL * HDD];
__device__ u16 g_vec_l[(size_t)BB * QLL * HDD];
__device__ float g_s[(size_t)BB * HH * QLL * KLL];
__device__ u8 g_bits[(size_t)BB * QLL * KLL / 8];   // bit-packed mask

// ---------------------------------------------------------------------------
// Primitives
// ---------------------------------------------------------------------------
__device__ __forceinline__ uint32_t smem_u32(const void* p) {
    uint32_t a;
    asm("{ .reg .u64 t; cvta.to.shared.u64 t, %1; cvt.u32.u64 %0, t; }" : "=r"(a) : "l"(p));
    return a;
}
__device__ __forceinline__ void ldsm4(uint32_t& r0, uint32_t& r1, uint32_t& r2, uint32_t& r3,
                                      uint32_t a) {
    asm volatile("ldmatrix.sync.aligned.m8n8.x4.shared.b16 {%0,%1,%2,%3}, [%4];"
                 : "=r"(r0), "=r"(r1), "=r"(r2), "=r"(r3) : "r"(a));
}
__device__ __forceinline__ void mma16816(float* c, const uint32_t* a, const uint32_t* b) {
    asm volatile("mma.sync.aligned.m16n8k16.row.col.f32.bf16.bf16.f32 "
                 "{%0,%1,%2,%3}, {%4,%5,%6,%7}, {%8,%9}, {%0,%1,%2,%3};"
                 : "+f"(c[0]), "+f"(c[1]), "+f"(c[2]), "+f"(c[3])
                 : "r"(a[0]), "r"(a[1]), "r"(a[2]), "r"(a[3]), "r"(b[0]), "r"(b[1]));
}
__device__ __forceinline__ void cpa16(uint32_t dst, const void* src) {
    asm volatile("cp.async.cg.shared.global [%0], [%1], 16;" :: "r"(dst), "l"(src));
}
#define CP_COMMIT() asm volatile("cp.async.commit_group;" ::: "memory")
#define CP_WAIT(n)  asm volatile("cp.async.wait_group %0;" :: "n"(n) : "memory")

__device__ __forceinline__ void split_bf16(float x, u16& h, u16& l) {
    __nv_bfloat16 hb = __float2bfloat16(x);
    h = __bfloat16_as_ushort(hb);
    l = __bfloat16_as_ushort(__float2bfloat16(x - __bfloat162float(hb)));
}
__device__ __forceinline__ void split4(float4 v, uint2& hi, uint2& lo) {
    u16 h0, h1, h2, h3, l0, l1, l2, l3;
    split_bf16(v.x, h0, l0); split_bf16(v.y, h1, l1);
    split_bf16(v.z, h2, l2); split_bf16(v.w, h3, l3);
    hi = make_uint2((uint32_t)h0 | ((uint32_t)h1 << 16), (uint32_t)h2 | ((uint32_t)h3 << 16));
    lo = make_uint2((uint32_t)l0 | ((uint32_t)l1 << 16), (uint32_t)l2 | ((uint32_t)l3 << 16));
}

// Warp-tile MMA step (32x32/warp, k16), 3-pass hi/lo, PASS-REORDERED so the
// 8 acc tiles interleave between reuses of the same accumulator (no RAW chain).
template<int P>
__device__ __forceinline__ void warp_mma(uint32_t sb, uint32_t aHi, uint32_t aLo,
                                         uint32_t bHi, uint32_t bLo,
                                         int kcc, int mw, int nw, int lane,
                                         float acc[2][4][4])
{
    uint32_t ah[2][4], al[2][4], bh[4][2], bl[4][2];
    #pragma unroll
    for (int i = 0; i < 2; i++) {
        int row = mw * 32 + i * 16 + (lane & 15);
        int col = kcc + ((lane >> 4) << 3);
        uint32_t off = (uint32_t)(row * P + col * 2);
        ldsm4(ah[i][0], ah[i][1], ah[i][2], ah[i][3], sb + aHi + off);
        ldsm4(al[i][0], al[i][1], al[i][2], al[i][3], sb + aLo + off);
    }
    #pragma unroll
    for (int jj = 0; jj < 2; jj++) {
        int n = nw * 32 + jj * 16 + ((lane >> 4) << 3) + (lane & 7);
        int k = kcc + (((lane >> 3) & 1) << 3);
        uint32_t off = (uint32_t)(n * P + k * 2);
        ldsm4(bh[jj*2][0], bh[jj*2][1], bh[jj*2+1][0], bh[jj*2+1][1], sb + bHi + off);
        ldsm4(bl[jj*2][0], bl[jj*2][1], bl[jj*2+1][0], bl[jj*2+1][1], sb + bLo + off);
    }
    // pass 1: hi*hi
    #pragma unroll
    for (int i = 0; i < 2; i++)
        #pragma unroll
        for (int j = 0; j < 4; j++)
            mma16816(acc[i][j], ah[i], bh[j]);
    // pass 2: hi*lo
    #pragma unroll
    for (int i = 0; i < 2; i++)
        #pragma unroll
        for (int j = 0; j < 4; j++)
            mma16816(acc[i][j], ah[i], bl[j]);
    // pass 3: lo*hi
    #pragma unroll
    for (int i = 0; i < 2; i++)
        #pragma unroll
        for (int j = 0; j < 4; j++)
            mma16816(acc[i][j], al[i], bh[j]);
}

// ---------------------------------------------------------------------------
// Convert / pack kernels
// ---------------------------------------------------------------------------
__global__ void cvt(const float* __restrict__ s, u16* __restrict__ dh,
                    u16* __restrict__ dl, int n)
{
    int i = (blockIdx.x * blockDim.x + threadIdx.x) * 4;
    if (i >= n) return;
    float4 v = *reinterpret_cast<const float4*>(s + i);
    uint2 h, l; split4(v, h, l);
    *reinterpret_cast<uint2*>(dh + i) = h;
    *reinterpret_cast<uint2*>(dl + i) = l;
}

__global__ void cvtT(const float* __restrict__ W, u16* __restrict__ th,
                     u16* __restrict__ tl)
{
    __shared__ float t[32][33];
    const int nb = blockIdx.x * 32, kb = blockIdx.y * 32;
    const int tx = threadIdx.x, ty = threadIdx.y;
    #pragma unroll
    for (int i = 0; i < 4; i++)
        t[ty + i * 8][tx] = W[(size_t)(kb + ty + i * 8) * 768 + nb + tx];
    __syncthreads();
    #pragma unroll
    for (int i = 0; i < 4; i++) {
        float v = t[tx][ty + i * 8];
        u16 h, l; split_bf16(v, h, l);
        size_t o = (size_t)(nb + ty + i * 8) * 768 + kb + tx;
        th[o] = h; tl[o] = l;
    }
}

// pack int32 mask -> bits (1 bit per element, bit j = element j within byte)
__global__ void packmask(const mask_t* __restrict__ m, u8* __restrict__ out)
{
    int i = blockIdx.x * blockDim.x + threadIdx.x;   // byte index
    const mask_t* p = m + (size_t)i * 8;
    unsigned b = 0;
    #pragma unroll
    for (int j = 0; j < 8; j += 4) {
        int4 v = *reinterpret_cast<const int4*>(p + j);
        b |= (v.x ? 1u : 0u) << j;
        b |= (v.y ? 1u : 0u) << (j + 1);
        b |= (v.z ? 1u : 0u) << (j + 2);
        b |= (v.w ? 1u : 0u) << (j + 3);
    }
    out[i] = (u8)b;
}

// ---------------------------------------------------------------------------
// tgemm (pure bf16, cp.async double-buffered)
// ---------------------------------------------------------------------------
#define GP 144
#define TG_AHI 0
#define TG_ALO (128 * GP)
#define TG_BHI (2 * 128 * GP)
#define TG_BLO (2 * 128 * GP + 64 * GP)
#define TG_STAGE (2 * 128 * GP + 2 * 64 * GP)   // 55296
#define TG_TOTAL (2 * TG_STAGE)                 // 110592

__global__ void __launch_bounds__(256)
tgemm(const u16* __restrict__ Ah, const u16* __restrict__ Al, long lda,
      const u16* __restrict__ Bh, const u16* __restrict__ Bl, long ldb,
      const float* __restrict__ bias, int mode,
      float* __restrict__ Cf, u16* __restrict__ C1h, u16* __restrict__ C1l,
      u16* __restrict__ C2h, u16* __restrict__ C2l,
      const float* __restrict__ add1, const float* __restrict__ add2,
      long ldc, int K)
{
    extern __shared__ char sm[];
    const uint32_t sb = smem_u32(sm);
    const int tid = threadIdx.x, wid = tid >> 5, lane = tid & 31;
    const int mw = wid >> 1, nw = wid & 1;
    const int m0 = blockIdx.y << 7;
    const int n0 = blockIdx.x << 6;
    const int nslab = K >> 6;

    auto issue = [&](int s, int st) {
        const uint32_t base = sb + st * TG_STAGE;
        const int k0 = s << 6;
        #pragma unroll
        for (int it = 0; it < 4; it++) {
            int id = it * 256 + tid;
            int m = id >> 3, c = id & 7;
            size_t src = (size_t)(m0 + m) * lda + k0 + c * 8;
            uint32_t dst = base + TG_AHI + m * GP + c * 16;
            cpa16(dst, Ah + src);
            cpa16(dst + (TG_ALO - TG_AHI), Al + src);
        }
        #pragma unroll
        for (int it = 0; it < 2; it++) {
            int id = it * 256 + tid;
            int n = id >> 3, c = id & 7;
            size_t src = (size_t)(n0 + n) * ldb + k0 + c * 8;
            uint32_t dst = base + TG_BHI + n * GP + c * 16;
            cpa16(dst, Bh + src);
            cpa16(dst + (TG_BLO - TG_BHI), Bl + src);
        }
    };

    issue(0, 0); CP_COMMIT();

    float acc[2][4][4] = {};
    for (int s = 0; s < nslab; s++) {
        if (s + 1 < nslab) { issue(s + 1, (s + 1) & 1); CP_COMMIT(); CP_WAIT(1); }
        else               { CP_WAIT(0); }
        __syncthreads();
        const uint32_t st = (uint32_t)((s & 1) * TG_STAGE);
        #pragma unroll
        for (int ks = 0; ks < 4; ks++)
            warp_mma<GP>(sb, st + TG_AHI, st + TG_ALO, st + TG_BHI, st + TG_BLO,
                         ks << 4, mw, nw, lane, acc);
        __syncthreads();
    }

    const int gid = lane >> 2, tg = lane & 3;
    #pragma unroll
    for (int i = 0; i < 2; i++)
        #pragma unroll
        for (int j = 0; j < 4; j++) {
            int c = n0 + nw * 32 + j * 8 + tg * 2;
            float b0 = bias ? bias[c] : 0.f;
            float b1 = bias ? bias[c + 1] : 0.f;
            #pragma unroll
            for (int eh = 0; eh < 2; eh++) {
                int r = m0 + mw * 32 + i * 16 + gid + 8 * eh;
                size_t base = (size_t)r * ldc + c;
                float v0 = acc[i][j][eh * 2 + 0] + b0;
                float v1 = acc[i][j][eh * 2 + 1] + b1;
                if (mode == 0) {
                    *reinterpret_cast<float2*>(Cf + base) = make_float2(v0, v1);
                } else if (mode == 1) {
                    u16 h0, l0, h1, l1;
                    split_bf16(v0, h0, l0); split_bf16(v1, h1, l1);
                    *reinterpret_cast<uint32_t*>(C1h + base) = (uint32_t)h0 | ((uint32_t)h1 << 16);
                    *reinterpret_cast<uint32_t*>(C1l + base) = (uint32_t)l0 | ((uint32_t)l1 << 16);
                } else {
                    u16 h0, l0, h1, l1;
                    split_bf16(v0 + add1[c], h0, l0); split_bf16(v1 + add1[c + 1], h1, l1);
                    *reinterpret_cast<uint32_t*>(C1h + base) = (uint32_t)h0 | ((uint32_t)h1 << 16);
                    *reinterpret_cast<uint32_t*>(C1l + base) = (uint32_t)l0 | ((uint32_t)l1 << 16);
                    split_bf16(v0 + add2[c], h0, l0); split_bf16(v1 + add2[c + 1], h1, l1);
                    *reinterpret_cast<uint32_t*>(C2h + base) = (uint32_t)h0 | ((uint32_t)h1 << 16);
                    *reinterpret_cast<uint32_t*>(C2l + base) = (uint32_t)l0 | ((uint32_t)l1 << 16);
                }
            }
        }
}

// ---------------------------------------------------------------------------
// tscore: S = (A' * B'^T)*SCALE -> g_s  (raw; mask applied in softmax)
// ---------------------------------------------------------------------------
#define SP 272
#define TS_AHI 0
#define TS_ALO (128 * SP)
#define TS_B   (2 * 128 * SP)
#define TS_BSTG (2 * 64 * SP)
#define TS_BLOD (64 * SP)
#define TS_TOTAL (TS_B + 2 * TS_BSTG)     // 139264

__global__ void __launch_bounds__(256)
tscore()
{
    extern __shared__ char sm[];
    const uint32_t sb = smem_u32(sm);
    const int tid = threadIdx.x, wid = tid >> 5, lane = tid & 31;
    const int mw = wid >> 1, nw = wid & 1;
    const int gid = lane >> 2, tg = lane & 3;
    const int bh = blockIdx.z;
    const int b3 = bh / HH, h3 = bh % HH;
    const int mp = bh + BB;
    const int bu = mp / (HH + 1), hh = mp % (HH + 1);
    const int has_bd = (hh != 0);
    const int hm1 = hh - 1;
    const int q0 = blockIdx.y << 7;

    #pragma unroll
    for (int it = 0; it < 8; it++) {
        int id = it * 256 + tid;
        int m = id >> 4, c = id & 15;
        uint4 hv, lv;
        if (c < 8) {
            size_t src = (size_t)(b3 * QLL + q0 + m) * HDD + h3 * DD + c * 8;
            hv = *reinterpret_cast<const uint4*>(g_qw_h + src);
            lv = *reinterpret_cast<const uint4*>(g_qw_l + src);
        } else if (has_bd) {
            size_t src = (size_t)(bu * QLL + q0 + m) * HDD + hm1 * DD + (c - 8) * 8;
            hv = *reinterpret_cast<const uint4*>(g_qr_h + src);
            lv = *reinterpret_cast<const uint4*>(g_qr_l + src);
        } else {
            hv = make_uint4(0u, 0u, 0u, 0u); lv = hv;
        }
        int off = m * SP + c * 16;
        *reinterpret_cast<uint4*>(sm + TS_AHI + off) = hv;
        *reinterpret_cast<uint4*>(sm + TS_ALO + off) = lv;
    }
    if (!has_bd) {
        uint4 z = make_uint4(0u, 0u, 0u, 0u);
        for (int id = tid; id < 64 * 8; id += 256) {
            int n = id >> 3, c = id & 7;
            int o = TS_B + n * SP + 128 + c * 16;
            *reinterpret_cast<uint4*>(sm + o) = z;
            *reinterpret_cast<uint4*>(sm + o + TS_BLOD) = z;
            *reinterpret_cast<uint4*>(sm + o + TS_BSTG) = z;
            *reinterpret_cast<uint4*>(sm + o + TS_BSTG + TS_BLOD) = z;
        }
    }

    auto issueB = [&](int kt, int st) {
        const uint32_t base = sb + TS_B + st * TS_BSTG;
        const int kc = kt << 6;
        const int nch = has_bd ? 16 : 8;
        const int tot = 64 * nch;
        for (int id = tid; id < tot; id += 256) {
            int n = id / nch, c = id % nch;
            uint32_t dst = base + n * SP + c * 16;
            if (c < 8) {
                size_t src = (size_t)(b3 * KLL + kc + n) * HDD + h3 * DD + c * 8;
                cpa16(dst, g_k_h + src);
                cpa16(dst + TS_BLOD, g_k_l + src);
            } else {
                size_t src = (size_t)(kc + n) * HDD + hm1 * DD + (c - 8) * 8;
                cpa16(dst, g_r_h + src);
                cpa16(dst + TS_BLOD, g_r_l + src);
            }
        }
    };

    issueB(0, 0); CP_COMMIT();

    for (int kt = 0; kt < 32; kt++) {
        if (kt + 1 < 32) { issueB(kt + 1, (kt + 1) & 1); CP_COMMIT(); CP_WAIT(1); }
        else             { CP_WAIT(0); }
        __syncthreads();

        float acc[2][4][4] = {};
        const uint32_t bst = (uint32_t)(TS_B + (kt & 1) * TS_BSTG);
        #pragma unroll
        for (int ks = 0; ks < 8; ks++)
            warp_mma<SP>(sb, TS_AHI, TS_ALO, bst, bst + TS_BLOD,
                         ks << 4, mw, nw, lane, acc);

        const int kc = kt << 6;
        #pragma unroll
        for (int i = 0; i < 2; i++)
            #pragma unroll
            for (int j = 0; j < 4; j++) {
                int q = q0 + mw * 32 + i * 16 + gid;
                int c = kc + nw * 32 + j * 8 + tg * 2;
                const size_t srow0 = ((size_t)bh * QLL + q) * KLL + c;
                *reinterpret_cast<float2*>(g_s + srow0) =
                    make_float2(acc[i][j][0] * SCALEF, acc[i][j][1] * SCALEF);
                *reinterpret_cast<float2*>(g_s + srow0 + 8 * KLL) =
                    make_float2(acc[i][j][2] * SCALEF, acc[i][j][3] * SCALEF);
            }
        __syncthreads();
    }
}

// ---------------------------------------------------------------------------
// Softmax with bit-packed mask: thread t handles 8 consecutive cols [8t, 8t+8)
// ---------------------------------------------------------------------------
__device__ __forceinline__ float warp_max(float v) {
    #pragma unroll
    for (int o = 16; o; o >>= 1) v = fmaxf(v, __shfl_xor_sync(0xffffffffu, v, o));
    return v;
}
__device__ __forceinline__ float warp_sum(float v) {
    #pragma unroll
    for (int o = 16; o; o >>= 1) v += __shfl_xor_sync(0xffffffffu, v, o);
    return v;
}

__global__ __launch_bounds__(256)
void softmax_kernel(const float* __restrict__ S, float* __restrict__ P)
{
    const size_t row = blockIdx.x;               // bh*QLL + q
    const int b3 = (int)(row / (HH * QLL));
    const int q  = (int)(row % QLL);
    const float* s = S + row * KLL;
    float*       p = P + row * KLL;
    const int tid = threadIdx.x;

    __shared__ float sh[8];
    const int wid = tid >> 5;
    const int lid = tid & 31;

    const unsigned bits = g_bits[((size_t)b3 * QLL + q) * (KLL / 8) + tid];

    float v[8];
    *reinterpret_cast<float4*>(v)     = *reinterpret_cast<const float4*>(s + tid * 8);
    *reinterpret_cast<float4*>(v + 4) = *reinterpret_cast<const float4*>(s + tid * 8 + 4);

    float m = -3.0e38f;
    #pragma unroll
    for (int i = 0; i < 8; i++) {
        if ((bits >> i) & 1u) v[i] = -3.0e38f;
        m = fmaxf(m, v[i]);
    }
    float wm = warp_max(m);
    if (lid == 0) sh[wid] = wm;
    __syncthreads();
    if (wid == 0) {
        float t = (lid < 8) ? sh[lid] : -3.0e38f;
        t = warp_max(t);
        if (lid == 0) sh[0] = t;
    }
    __syncthreads();
    const float bm = sh[0];

    float lsum = 0.0f;
    #pragma unroll
    for (int i = 0; i < 8; i++) {
        v[i] = __expf(v[i] - bm);      // masked: exp(-3e38 - bm) underflows to 0
        lsum += v[i];
    }
    float ws = warp_sum(lsum);
    __syncthreads();
    if (lid == 0) sh[wid] = ws;
    __syncthreads();
    if (wid == 0) {
        float t = (lid < 8) ? sh[lid] : 0.0f;
        t = warp_sum(t);
        if (lid == 0) sh[0] = t;
    }
    __syncthreads();
    const float inv = 1.0f / sh[0];

    #pragma unroll
    for (int i = 0; i < 8; i++) v[i] *= inv;
    *reinterpret_cast<float4*>(p + tid * 8)     = *reinterpret_cast<float4*>(v);
    *reinterpret_cast<float4*>(p + tid * 8 + 4) = *reinterpret_cast<float4*>(v + 4);
}

// ---------------------------------------------------------------------------
// pv: vec = prob @ V_h ; epilogue writes vec as bf16 hi/lo
// ---------------------------------------------------------------------------
__global__ void __launch_bounds__(256, 2)
pv_kernel(const float* __restrict__ prob)
{
    extern __shared__ char sm[];
    const uint32_t sb = smem_u32(sm);
    const int tid = threadIdx.x, wid = tid >> 5, lane = tid & 31;
    const int mw = wid >> 1, nw = wid & 1;
    const int bh = blockIdx.z;
    const int b3 = bh / HH, h3 = bh % HH;
    const int q0 = blockIdx.y << 7;

    float acc[2][4][4] = {};

    for (int kt = 0; kt < 32; kt++) {
        const int kc = kt << 6;
        #pragma unroll
        for (int it = 0; it < 8; it++) {
            int idx = (it * 256 + tid) << 2;
            int m = idx >> 6, k = idx & 63;
            float4 p4 = *reinterpret_cast<const float4*>(
                prob + ((size_t)bh * QLL + q0 + m) * KLL + kc + k);
            uint2 hi, lo; split4(p4, hi, lo);
            int off = m * GP + k * 2;
            *reinterpret_cast<uint2*>(sm + TG_AHI + off) = hi;
            *reinterpret_cast<uint2*>(sm + TG_ALO + off) = lo;
        }
        #pragma unroll
        for (int it = 0; it < 16; it++) {
            int idx = it * 256 + tid;
            int k = idx >> 6, n = idx & 63;
            size_t base = (size_t)(b3 * KLL + kc + k) * HDD + h3 * DD + n;
            int off = n * GP + k * 2;
            *reinterpret_cast<u16*>(sm + TG_BHI + off) = g_v_h[base];
            *reinterpret_cast<u16*>(sm + TG_BLO + off) = g_v_l[base];
        }
        __syncthreads();
        #pragma unroll
        for (int ks = 0; ks < 4; ks++)
            warp_mma<GP>(sb, TG_AHI, TG_ALO, TG_BHI, TG_BLO, ks << 4, mw, nw, lane, acc);
        __syncthreads();
    }

    const int gid = lane >> 2, tg = lane & 3;
    #pragma unroll
    for (int i = 0; i < 2; i++)
        #pragma unroll
        for (int j = 0; j < 4; j++) {
            int c = nw * 32 + j * 8 + tg * 2;
            #pragma unroll
            for (int eh = 0; eh < 2; eh++) {
                int q = q0 + mw * 32 + i * 16 + gid + 8 * eh;
                size_t base = (size_t)(b3 * QLL + q) * HDD + h3 * DD + c;
                u16 h0, l0, h1, l1;
                split_bf16(acc[i][j][eh * 2 + 0], h0, l0);
                split_bf16(acc[i][j][eh * 2 + 1], h1, l1);
                *reinterpret_cast<uint32_t*>(g_vec_h + base) = (uint32_t)h0 | ((uint32_t)h1 << 16);
                *reinterpret_cast<uint32_t*>(g_vec_l + base) = (uint32_t)l0 | ((uint32_t)l1 << 16);
            }
        }
}

// ---------------------------------------------------------------------------
// Launch
// ---------------------------------------------------------------------------
extern "C" void kernel_launch(void* const* d_in, const int* in_sizes, int n_in,
                              void* d_out, int out_size)
{
    (void)in_sizes; (void)n_in; (void)out_size;

    const float*  Q    = (const float*)d_in[0];
    const float*  Kin  = (const float*)d_in[1];
    const float*  Vin  = (const float*)d_in[2];
    const float*  pos  = (const float*)d_in[3];
    const float*  rwb  = (const float*)d_in[4];
    const float*  rrb  = (const float*)d_in[5];
    const mask_t* mask = (const mask_t*)d_in[6];
    // d_in[7] = mems (unused)
    const float*  Wq = (const float*)d_in[8];
    const float*  bq = (const float*)d_in[9];
    const float*  Wk = (const float*)d_in[10];
    const float*  bk = (const float*)d_in[11];
    const float*  Wv = (const float*)d_in[12];
    const float*  bv = (const float*)d_in[13];
    const float*  Wr = (const float*)d_in[14];
    const float*  Wo = (const float*)d_in[15];
    const float*  bo = (const float*)d_in[16];

    float* out  = (float*)d_out;
    float* prob = out + (size_t)BB * QLL * EE;

    u16 *xh, *xl, *wh, *wl;
    u16 *qwh, *qwl, *qrh, *qrl, *kh, *kl, *vh, *vl, *rh, *rl, *vech, *vecl;
    float *ps; u8 *bits;
    cudaGetSymbolAddress((void**)&xh, g_x_h);
    cudaGetSymbolAddress((void**)&xl, g_x_l);
    cudaGetSymbolAddress((void**)&wh, g_w_h);
    cudaGetSymbolAddress((void**)&wl, g_w_l);
    cudaGetSymbolAddress((void**)&qwh, g_qw_h);
    cudaGetSymbolAddress((void**)&qwl, g_qw_l);
    cudaGetSymbolAddress((void**)&qrh, g_qr_h);
    cudaGetSymbolAddress((void**)&qrl, g_qr_l);
    cudaGetSymbolAddress((void**)&kh,  g_k_h);
    cudaGetSymbolAddress((void**)&kl,  g_k_l);
    cudaGetSymbolAddress((void**)&vh,  g_v_h);
    cudaGetSymbolAddress((void**)&vl,  g_v_l);
    cudaGetSymbolAddress((void**)&rh,  g_r_h);
    cudaGetSymbolAddress((void**)&rl,  g_r_l);
    cudaGetSymbolAddress((void**)&vech, g_vec_h);
    cudaGetSymbolAddress((void**)&vecl, g_vec_l);
    cudaGetSymbolAddress((void**)&ps,  g_s);
    cudaGetSymbolAddress((void**)&bits, g_bits);

    cudaFuncSetAttribute(tgemm,     cudaFuncAttributeMaxDynamicSharedMemorySize, TG_TOTAL);
    cudaFuncSetAttribute(tscore,    cudaFuncAttributeMaxDynamicSharedMemorySize, TS_TOTAL);
    cudaFuncSetAttribute(pv_kernel, cudaFuncAttributeMaxDynamicSharedMemorySize, TG_STAGE);

    const dim3 blk(256);

    // Converts + mask pack
    cvt<<<(2048 * 768) / 1024, blk>>>(Q,   xh + XQ, xl + XQ, 2048 * 768);
    cvt<<<(4096 * 768) / 1024, blk>>>(Kin, xh + XK, xl + XK, 4096 * 768);
    cvt<<<(4096 * 768) / 1024, blk>>>(Vin, xh + XV, xl + XV, 4096 * 768);
    cvt<<<(2048 * 768) / 1024, blk>>>(pos, xh + XR, xl + XR, 2048 * 768);
    dim3 tgrid(24, 24), tblk(32, 8);
    cvtT<<<tgrid, tblk>>>(Wq, wh + WQO, wl + WQO);
    cvtT<<<tgrid, tblk>>>(Wk, wh + WKO, wl + WKO);
    cvtT<<<tgrid, tblk>>>(Wv, wh + WVO, wl + WVO);
    cvtT<<<tgrid, tblk>>>(Wr, wh + WRO, wl + WRO);
    cvtT<<<tgrid, tblk>>>(Wo, wh + WOO, wl + WOO);
    packmask<<<(BB * QLL * KLL / 8) / 256, blk>>>(mask, bits);

    // Projections
    tgemm<<<dim3(12, 16), blk, TG_TOTAL>>>(
        xh + XQ, xl + XQ, EE, wh + WQO, wl + WQO, EE, bq, 2,
        nullptr, qwh, qwl, qrh, qrl, rwb, rrb, HDD, EE);
    tgemm<<<dim3(12, 32), blk, TG_TOTAL>>>(
        xh + XK, xl + XK, EE, wh + WKO, wl + WKO, EE, bk, 1,
        nullptr, kh, kl, nullptr, nullptr, nullptr, nullptr, HDD, EE);
    tgemm<<<dim3(12, 32), blk, TG_TOTAL>>>(
        xh + XV, xl + XV, EE, wh + WVO, wl + WVO, EE, bv, 1,
        nullptr, vh, vl, nullptr, nullptr, nullptr, nullptr, HDD, EE);
    tgemm<<<dim3(12, 16), blk, TG_TOTAL>>>(
        xh + XR, xl + XR, EE, wh + WRO, wl + WRO, EE, nullptr, 1,
        nullptr, rh, rl, nullptr, nullptr, nullptr, nullptr, HDD, EE);

    // Scores (raw, scaled)
    tscore<<<dim3(1, QLL / 128, BB * HH), blk, TS_TOTAL>>>();

    // Softmax (mask applied here) -> prob
    softmax_kernel<<<BB * HH * QLL, blk>>>(ps, prob);

    // PV
    pv_kernel<<<dim3(1, QLL / 128, BB * HH), blk, TG_STAGE>>>(prob);

    // Output projection
    tgemm<<<dim3(12, 16), blk, TG_TOTAL>>>(
        vech, vecl, HDD, wh + WOO, wl + WOO, HDD, bo, 0,
        out, nullptr, nullptr, nullptr, nullptr, nullptr, nullptr, EE, HDD);
}

// round 8
// speedup vs baseline: 1.5336x; 1.0853x over previous
#include <cuda_runtime.h>
#include <cuda_bf16.h>
#include <stdint.h>

// ---------------------------------------------------------------------------
// Problem constants
// ---------------------------------------------------------------------------
#define BB   2
#define HH   12
#define DD   64
#define EE   768
#define QLL  1024
#define KLL  2048
#define HDD  768
#define SCALEF 0.125f
typedef int mask_t;
typedef unsigned short u16;
typedef unsigned char u8;

// ---------------------------------------------------------------------------
// Scratch (device globals)
// ---------------------------------------------------------------------------
#define XQ 0
#define XK ((size_t)2048 * 768)
#define XV ((size_t)6144 * 768)
#define XR ((size_t)10240 * 768)
__device__ u16 g_x_h[(size_t)12288 * 768];
__device__ u16 g_x_l[(size_t)12288 * 768];
#define WQO ((size_t)0)
#define WKO ((size_t)1 * 768 * 768)
#define WVO ((size_t)2 * 768 * 768)
#define WRO ((size_t)3 * 768 * 768)
#define WOO ((size_t)4 * 768 * 768)
__device__ u16 g_w_h[(size_t)5 * 768 * 768];
__device__ u16 g_w_l[(size_t)5 * 768 * 768];
__device__ u16 g_qw_h[(size_t)BB * QLL * HDD];
__device__ u16 g_qw_l[(size_t)BB * QLL * HDD];
__device__ u16 g_qr_h[(size_t)BB * QLL * HDD];
__device__ u16 g_qr_l[(size_t)BB * QLL * HDD];
__device__ u16 g_k_h [(size_t)BB * KLL * HDD];
__device__ u16 g_k_l [(size_t)BB * KLL * HDD];
__device__ u16 g_v_h [(size_t)BB * KLL * HDD];
__device__ u16 g_v_l [(size_t)BB * KLL * HDD];
__device__ u16 g_r_h [(size_t)KLL * HDD];
__device__ u16 g_r_l [(size_t)KLL * HDD];
__device__ u16 g_vec_h[(size_t)BB * QLL * HDD];
__device__ u16 g_vec_l[(size_t)BB * QLL * HDD];
__device__ float g_pv[3][(size_t)BB * QLL * HDD];   // pv k-split partials
__device__ float g_s[(size_t)BB * HH * QLL * KLL];
__device__ u8 g_bits[(size_t)BB * QLL * KLL / 8];

// ---------------------------------------------------------------------------
// Primitives
// ---------------------------------------------------------------------------
__device__ __forceinline__ uint32_t smem_u32(const void* p) {
    uint32_t a;
    asm("{ .reg .u64 t; cvta.to.shared.u64 t, %1; cvt.u32.u64 %0, t; }" : "=r"(a) : "l"(p));
    return a;
}
__device__ __forceinline__ void ldsm4(uint32_t& r0, uint32_t& r1, uint32_t& r2, uint32_t& r3,
                                      uint32_t a) {
    asm volatile("ldmatrix.sync.aligned.m8n8.x4.shared.b16 {%0,%1,%2,%3}, [%4];"
                 : "=r"(r0), "=r"(r1), "=r"(r2), "=r"(r3) : "r"(a));
}
__device__ __forceinline__ void mma16816(float* c, const uint32_t* a, const uint32_t* b) {
    asm volatile("mma.sync.aligned.m16n8k16.row.col.f32.bf16.bf16.f32 "
                 "{%0,%1,%2,%3}, {%4,%5,%6,%7}, {%8,%9}, {%0,%1,%2,%3};"
                 : "+f"(c[0]), "+f"(c[1]), "+f"(c[2]), "+f"(c[3])
                 : "r"(a[0]), "r"(a[1]), "r"(a[2]), "r"(a[3]), "r"(b[0]), "r"(b[1]));
}
__device__ __forceinline__ void cpa16(uint32_t dst, const void* src) {
    asm volatile("cp.async.cg.shared.global [%0], [%1], 16;" :: "r"(dst), "l"(src));
}
#define CP_COMMIT() asm volatile("cp.async.commit_group;" ::: "memory")
#define CP_WAIT(n)  asm volatile("cp.async.wait_group %0;" :: "n"(n) : "memory")

__device__ __forceinline__ void split_bf16(float x, u16& h, u16& l) {
    __nv_bfloat16 hb = __float2bfloat16(x);
    h = __bfloat16_as_ushort(hb);
    l = __bfloat16_as_ushort(__float2bfloat16(x - __bfloat162float(hb)));
}
__device__ __forceinline__ void split4(float4 v, uint2& hi, uint2& lo) {
    u16 h0, h1, h2, h3, l0, l1, l2, l3;
    split_bf16(v.x, h0, l0); split_bf16(v.y, h1, l1);
    split_bf16(v.z, h2, l2); split_bf16(v.w, h3, l3);
    hi = make_uint2((uint32_t)h0 | ((uint32_t)h1 << 16), (uint32_t)h2 | ((uint32_t)h3 << 16));
    lo = make_uint2((uint32_t)l0 | ((uint32_t)l1 << 16), (uint32_t)l2 | ((uint32_t)l3 << 16));
}

// Warp-tile MMA step (32x32/warp, k16), 3-pass hi/lo, pass-reordered.
template<int P>
__device__ __forceinline__ void warp_mma(uint32_t sb, uint32_t aHi, uint32_t aLo,
                                         uint32_t bHi, uint32_t bLo,
                                         int kcc, int mw, int nw, int lane,
                                         float acc[2][4][4])
{
    uint32_t ah[2][4], al[2][4], bh[4][2], bl[4][2];
    #pragma unroll
    for (int i = 0; i < 2; i++) {
        int row = mw * 32 + i * 16 + (lane & 15);
        int col = kcc + ((lane >> 4) << 3);
        uint32_t off = (uint32_t)(row * P + col * 2);
        ldsm4(ah[i][0], ah[i][1], ah[i][2], ah[i][3], sb + aHi + off);
        ldsm4(al[i][0], al[i][1], al[i][2], al[i][3], sb + aLo + off);
    }
    #pragma unroll
    for (int jj = 0; jj < 2; jj++) {
        int n = nw * 32 + jj * 16 + ((lane >> 4) << 3) + (lane & 7);
        int k = kcc + (((lane >> 3) & 1) << 3);
        uint32_t off = (uint32_t)(n * P + k * 2);
        ldsm4(bh[jj*2][0], bh[jj*2][1], bh[jj*2+1][0], bh[jj*2+1][1], sb + bHi + off);
        ldsm4(bl[jj*2][0], bl[jj*2][1], bl[jj*2+1][0], bl[jj*2+1][1], sb + bLo + off);
    }
    #pragma unroll
    for (int i = 0; i < 2; i++)
        #pragma unroll
        for (int j = 0; j < 4; j++)
            mma16816(acc[i][j], ah[i], bh[j]);
    #pragma unroll
    for (int i = 0; i < 2; i++)
        #pragma unroll
        for (int j = 0; j < 4; j++)
            mma16816(acc[i][j], ah[i], bl[j]);
    #pragma unroll
    for (int i = 0; i < 2; i++)
        #pragma unroll
        for (int j = 0; j < 4; j++)
            mma16816(acc[i][j], al[i], bh[j]);
}

// ---------------------------------------------------------------------------
// Convert / pack kernels
// ---------------------------------------------------------------------------
__global__ void cvt(const float* __restrict__ s, u16* __restrict__ dh,
                    u16* __restrict__ dl, int n)
{
    int i = (blockIdx.x * blockDim.x + threadIdx.x) * 4;
    if (i >= n) return;
    float4 v = *reinterpret_cast<const float4*>(s + i);
    uint2 h, l; split4(v, h, l);
    *reinterpret_cast<uint2*>(dh + i) = h;
    *reinterpret_cast<uint2*>(dl + i) = l;
}

__global__ void cvtT(const float* __restrict__ W, u16* __restrict__ th,
                     u16* __restrict__ tl)
{
    __shared__ float t[32][33];
    const int nb = blockIdx.x * 32, kb = blockIdx.y * 32;
    const int tx = threadIdx.x, ty = threadIdx.y;
    #pragma unroll
    for (int i = 0; i < 4; i++)
        t[ty + i * 8][tx] = W[(size_t)(kb + ty + i * 8) * 768 + nb + tx];
    __syncthreads();
    #pragma unroll
    for (int i = 0; i < 4; i++) {
        float v = t[tx][ty + i * 8];
        u16 h, l; split_bf16(v, h, l);
        size_t o = (size_t)(nb + ty + i * 8) * 768 + kb + tx;
        th[o] = h; tl[o] = l;
    }
}

__global__ void packmask(const mask_t* __restrict__ m, u8* __restrict__ out)
{
    int i = blockIdx.x * blockDim.x + threadIdx.x;
    const mask_t* p = m + (size_t)i * 8;
    unsigned b = 0;
    #pragma unroll
    for (int j = 0; j < 8; j += 4) {
        int4 v = *reinterpret_cast<const int4*>(p + j);
        b |= (v.x ? 1u : 0u) << j;
        b |= (v.y ? 1u : 0u) << (j + 1);
        b |= (v.z ? 1u : 0u) << (j + 2);
        b |= (v.w ? 1u : 0u) << (j + 3);
    }
    out[i] = (u8)b;
}

// sum 3 pv partials, split to bf16 hi/lo
__global__ void vecfin(u16* __restrict__ dh, u16* __restrict__ dl)
{
    int i = (blockIdx.x * blockDim.x + threadIdx.x) * 4;
    float4 a = *reinterpret_cast<const float4*>(&g_pv[0][i]);
    float4 b = *reinterpret_cast<const float4*>(&g_pv[1][i]);
    float4 c = *reinterpret_cast<const float4*>(&g_pv[2][i]);
    a.x += b.x + c.x; a.y += b.y + c.y; a.z += b.z + c.z; a.w += b.w + c.w;
    uint2 h, l; split4(a, h, l);
    *reinterpret_cast<uint2*>(dh + i) = h;
    *reinterpret_cast<uint2*>(dl + i) = l;
}

// ---------------------------------------------------------------------------
// tgemm: k-slab 32, 2 stages, 2 CTAs/SM.  Pitch 80B (conflict-free for ldsm).
// ---------------------------------------------------------------------------
#define GP32 80
#define T2_AHI 0
#define T2_ALO (128 * GP32)                 // 10240
#define T2_BHI (2 * 128 * GP32)             // 20480
#define T2_BLO (2 * 128 * GP32 + 64 * GP32) // 25600
#define T2_STAGE (2 * 128 * GP32 + 2 * 64 * GP32)  // 30720
#define T2_TOTAL (2 * T2_STAGE)                    // 61440

__global__ void __launch_bounds__(256, 2)
tgemm(const u16* __restrict__ Ah, const u16* __restrict__ Al, long lda,
      const u16* __restrict__ Bh, const u16* __restrict__ Bl, long ldb,
      const float* __restrict__ bias, int mode,
      float* __restrict__ Cf, u16* __restrict__ C1h, u16* __restrict__ C1l,
      u16* __restrict__ C2h, u16* __restrict__ C2l,
      const float* __restrict__ add1, const float* __restrict__ add2,
      long ldc, int K)
{
    extern __shared__ char sm[];
    const uint32_t sb = smem_u32(sm);
    const int tid = threadIdx.x, wid = tid >> 5, lane = tid & 31;
    const int mw = wid >> 1, nw = wid & 1;
    const int m0 = blockIdx.y << 7;
    const int n0 = blockIdx.x << 6;
    const int nslab = K >> 5;

    auto issue = [&](int s, int st) {
        const uint32_t base = sb + st * T2_STAGE;
        const int k0 = s << 5;
        #pragma unroll
        for (int it = 0; it < 2; it++) {
            int id = it * 256 + tid;           // 0..511
            int m = id >> 2, c = id & 3;
            size_t src = (size_t)(m0 + m) * lda + k0 + c * 8;
            uint32_t dst = base + T2_AHI + m * GP32 + c * 16;
            cpa16(dst, Ah + src);
            cpa16(dst + (T2_ALO - T2_AHI), Al + src);
        }
        {
            int id = tid;                      // 0..255
            int n = id >> 2, c = id & 3;
            size_t src = (size_t)(n0 + n) * ldb + k0 + c * 8;
            uint32_t dst = base + T2_BHI + n * GP32 + c * 16;
            cpa16(dst, Bh + src);
            cpa16(dst + (T2_BLO - T2_BHI), Bl + src);
        }
    };

    issue(0, 0); CP_COMMIT();

    float acc[2][4][4] = {};
    for (int s = 0; s < nslab; s++) {
        if (s + 1 < nslab) { issue(s + 1, (s + 1) & 1); CP_COMMIT(); CP_WAIT(1); }
        else               { CP_WAIT(0); }
        __syncthreads();
        const uint32_t st = (uint32_t)((s & 1) * T2_STAGE);
        #pragma unroll
        for (int ks = 0; ks < 2; ks++)
            warp_mma<GP32>(sb, st + T2_AHI, st + T2_ALO, st + T2_BHI, st + T2_BLO,
                           ks << 4, mw, nw, lane, acc);
        __syncthreads();
    }

    const int gid = lane >> 2, tg = lane & 3;
    #pragma unroll
    for (int i = 0; i < 2; i++)
        #pragma unroll
        for (int j = 0; j < 4; j++) {
            int c = n0 + nw * 32 + j * 8 + tg * 2;
            float b0 = bias ? bias[c] : 0.f;
            float b1 = bias ? bias[c + 1] : 0.f;
            #pragma unroll
            for (int eh = 0; eh < 2; eh++) {
                int r = m0 + mw * 32 + i * 16 + gid + 8 * eh;
                size_t base = (size_t)r * ldc + c;
                float v0 = acc[i][j][eh * 2 + 0] + b0;
                float v1 = acc[i][j][eh * 2 + 1] + b1;
                if (mode == 0) {
                    *reinterpret_cast<float2*>(Cf + base) = make_float2(v0, v1);
                } else if (mode == 1) {
                    u16 h0, l0, h1, l1;
                    split_bf16(v0, h0, l0); split_bf16(v1, h1, l1);
                    *reinterpret_cast<uint32_t*>(C1h + base) = (uint32_t)h0 | ((uint32_t)h1 << 16);
                    *reinterpret_cast<uint32_t*>(C1l + base) = (uint32_t)l0 | ((uint32_t)l1 << 16);
                } else {
                    u16 h0, l0, h1, l1;
                    split_bf16(v0 + add1[c], h0, l0); split_bf16(v1 + add1[c + 1], h1, l1);
                    *reinterpret_cast<uint32_t*>(C1h + base) = (uint32_t)h0 | ((uint32_t)h1 << 16);
                    *reinterpret_cast<uint32_t*>(C1l + base) = (uint32_t)l0 | ((uint32_t)l1 << 16);
                    split_bf16(v0 + add2[c], h0, l0); split_bf16(v1 + add2[c + 1], h1, l1);
                    *reinterpret_cast<uint32_t*>(C2h + base) = (uint32_t)h0 | ((uint32_t)h1 << 16);
                    *reinterpret_cast<uint32_t*>(C2l + base) = (uint32_t)l0 | ((uint32_t)l1 << 16);
                }
            }
        }
}

// ---------------------------------------------------------------------------
// tscore: S = (A' * B'^T)*SCALE -> g_s (raw), 3-way k-split over blockIdx.x
// ---------------------------------------------------------------------------
#define SP 272
#define TS_AHI 0
#define TS_ALO (128 * SP)
#define TS_B   (2 * 128 * SP)
#define TS_BSTG (2 * 64 * SP)
#define TS_BLOD (64 * SP)
#define TS_TOTAL (TS_B + 2 * TS_BSTG)     // 139264

__global__ void __launch_bounds__(256)
tscore()
{
    extern __shared__ char sm[];
    const uint32_t sb = smem_u32(sm);
    const int tid = threadIdx.x, wid = tid >> 5, lane = tid & 31;
    const int mw = wid >> 1, nw = wid & 1;
    const int gid = lane >> 2, tg = lane & 3;
    const int bh = blockIdx.z;
    const int b3 = bh / HH, h3 = bh % HH;
    const int mp = bh + BB;
    const int bu = mp / (HH + 1), hh = mp % (HH + 1);
    const int has_bd = (hh != 0);
    const int hm1 = hh - 1;
    const int q0 = blockIdx.y << 7;
    const int ksp = blockIdx.x;
    const int kt0 = (ksp * 32) / 3, kt1 = ((ksp + 1) * 32) / 3;

    #pragma unroll
    for (int it = 0; it < 8; it++) {
        int id = it * 256 + tid;
        int m = id >> 4, c = id & 15;
        uint4 hv, lv;
        if (c < 8) {
            size_t src = (size_t)(b3 * QLL + q0 + m) * HDD + h3 * DD + c * 8;
            hv = *reinterpret_cast<const uint4*>(g_qw_h + src);
            lv = *reinterpret_cast<const uint4*>(g_qw_l + src);
        } else if (has_bd) {
            size_t src = (size_t)(bu * QLL + q0 + m) * HDD + hm1 * DD + (c - 8) * 8;
            hv = *reinterpret_cast<const uint4*>(g_qr_h + src);
            lv = *reinterpret_cast<const uint4*>(g_qr_l + src);
        } else {
            hv = make_uint4(0u, 0u, 0u, 0u); lv = hv;
        }
        int off = m * SP + c * 16;
        *reinterpret_cast<uint4*>(sm + TS_AHI + off) = hv;
        *reinterpret_cast<uint4*>(sm + TS_ALO + off) = lv;
    }
    if (!has_bd) {
        uint4 z = make_uint4(0u, 0u, 0u, 0u);
        for (int id = tid; id < 64 * 8; id += 256) {
            int n = id >> 3, c = id & 7;
            int o = TS_B + n * SP + 128 + c * 16;
            *reinterpret_cast<uint4*>(sm + o) = z;
            *reinterpret_cast<uint4*>(sm + o + TS_BLOD) = z;
            *reinterpret_cast<uint4*>(sm + o + TS_BSTG) = z;
            *reinterpret_cast<uint4*>(sm + o + TS_BSTG + TS_BLOD) = z;
        }
    }

    auto issueB = [&](int kt, int st) {
        const uint32_t base = sb + TS_B + st * TS_BSTG;
        const int kc = kt << 6;
        const int nch = has_bd ? 16 : 8;
        const int tot = 64 * nch;
        for (int id = tid; id < tot; id += 256) {
            int n = id / nch, c = id % nch;
            uint32_t dst = base + n * SP + c * 16;
            if (c < 8) {
                size_t src = (size_t)(b3 * KLL + kc + n) * HDD + h3 * DD + c * 8;
                cpa16(dst, g_k_h + src);
                cpa16(dst + TS_BLOD, g_k_l + src);
            } else {
                size_t src = (size_t)(kc + n) * HDD + hm1 * DD + (c - 8) * 8;
                cpa16(dst, g_r_h + src);
                cpa16(dst + TS_BLOD, g_r_l + src);
            }
        }
    };

    issueB(kt0, 0); CP_COMMIT();

    for (int kt = kt0; kt < kt1; kt++) {
        const int stg = (kt - kt0) & 1;
        if (kt + 1 < kt1) { issueB(kt + 1, stg ^ 1); CP_COMMIT(); CP_WAIT(1); }
        else              { CP_WAIT(0); }
        __syncthreads();

        float acc[2][4][4] = {};
        const uint32_t bst = (uint32_t)(TS_B + stg * TS_BSTG);
        #pragma unroll
        for (int ks = 0; ks < 8; ks++)
            warp_mma<SP>(sb, TS_AHI, TS_ALO, bst, bst + TS_BLOD,
                         ks << 4, mw, nw, lane, acc);

        const int kc = kt << 6;
        #pragma unroll
        for (int i = 0; i < 2; i++)
            #pragma unroll
            for (int j = 0; j < 4; j++) {
                int q = q0 + mw * 32 + i * 16 + gid;
                int c = kc + nw * 32 + j * 8 + tg * 2;
                const size_t srow0 = ((size_t)bh * QLL + q) * KLL + c;
                *reinterpret_cast<float2*>(g_s + srow0) =
                    make_float2(acc[i][j][0] * SCALEF, acc[i][j][1] * SCALEF);
                *reinterpret_cast<float2*>(g_s + srow0 + 8 * KLL) =
                    make_float2(acc[i][j][2] * SCALEF, acc[i][j][3] * SCALEF);
            }
        __syncthreads();
    }
}

// ---------------------------------------------------------------------------
// Softmax with bit-packed mask
// ---------------------------------------------------------------------------
__device__ __forceinline__ float warp_max(float v) {
    #pragma unroll
    for (int o = 16; o; o >>= 1) v = fmaxf(v, __shfl_xor_sync(0xffffffffu, v, o));
    return v;
}
__device__ __forceinline__ float warp_sum(float v) {
    #pragma unroll
    for (int o = 16; o; o >>= 1) v += __shfl_xor_sync(0xffffffffu, v, o);
    return v;
}

__global__ __launch_bounds__(256)
void softmax_kernel(const float* __restrict__ S, float* __restrict__ P)
{
    const size_t row = blockIdx.x;
    const int b3 = (int)(row / (HH * QLL));
    const int q  = (int)(row % QLL);
    const float* s = S + row * KLL;
    float*       p = P + row * KLL;
    const int tid = threadIdx.x;

    __shared__ float sh[8];
    const int wid = tid >> 5;
    const int lid = tid & 31;

    const unsigned bits = g_bits[((size_t)b3 * QLL + q) * (KLL / 8) + tid];

    float v[8];
    *reinterpret_cast<float4*>(v)     = *reinterpret_cast<const float4*>(s + tid * 8);
    *reinterpret_cast<float4*>(v + 4) = *reinterpret_cast<const float4*>(s + tid * 8 + 4);

    float m = -3.0e38f;
    #pragma unroll
    for (int i = 0; i < 8; i++) {
        if ((bits >> i) & 1u) v[i] = -3.0e38f;
        m = fmaxf(m, v[i]);
    }
    float wm = warp_max(m);
    if (lid == 0) sh[wid] = wm;
    __syncthreads();
    if (wid == 0) {
        float t = (lid < 8) ? sh[lid] : -3.0e38f;
        t = warp_max(t);
        if (lid == 0) sh[0] = t;
    }
    __syncthreads();
    const float bm = sh[0];

    float lsum = 0.0f;
    #pragma unroll
    for (int i = 0; i < 8; i++) {
        v[i] = __expf(v[i] - bm);
        lsum += v[i];
    }
    float ws = warp_sum(lsum);
    __syncthreads();
    if (lid == 0) sh[wid] = ws;
    __syncthreads();
    if (wid == 0) {
        float t = (lid < 8) ? sh[lid] : 0.0f;
        t = warp_sum(t);
        if (lid == 0) sh[0] = t;
    }
    __syncthreads();
    const float inv = 1.0f / sh[0];

    #pragma unroll
    for (int i = 0; i < 8; i++) v[i] *= inv;
    *reinterpret_cast<float4*>(p + tid * 8)     = *reinterpret_cast<float4*>(v);
    *reinterpret_cast<float4*>(p + tid * 8 + 4) = *reinterpret_cast<float4*>(v + 4);
}

// ---------------------------------------------------------------------------
// pv: vec_partial[ksp] = prob[:, ktile range] @ V_h  (3-way k-split, fp32 out)
// ---------------------------------------------------------------------------
#define GP 144
#define PV_AHI 0
#define PV_ALO (128 * GP)
#define PV_BHI (2 * 128 * GP)
#define PV_BLO (2 * 128 * GP + 64 * GP)
#define PV_TOTAL (2 * 128 * GP + 2 * 64 * GP)   // 55296

__global__ void __launch_bounds__(256, 2)
pv_kernel(const float* __restrict__ prob)
{
    extern __shared__ char sm[];
    const uint32_t sb = smem_u32(sm);
    const int tid = threadIdx.x, wid = tid >> 5, lane = tid & 31;
    const int mw = wid >> 1, nw = wid & 1;
    const int bh = blockIdx.z;
    const int b3 = bh / HH, h3 = bh % HH;
    const int q0 = blockIdx.y << 7;
    const int ksp = blockIdx.x;
    const int kt0 = (ksp * 32) / 3, kt1 = ((ksp + 1) * 32) / 3;

    float acc[2][4][4] = {};

    for (int kt = kt0; kt < kt1; kt++) {
        const int kc = kt << 6;
        #pragma unroll
        for (int it = 0; it < 8; it++) {
            int idx = (it * 256 + tid) << 2;
            int m = idx >> 6, k = idx & 63;
            float4 p4 = *reinterpret_cast<const float4*>(
                prob + ((size_t)bh * QLL + q0 + m) * KLL + kc + k);
            uint2 hi, lo; split4(p4, hi, lo);
            int off = m * GP + k * 2;
            *reinterpret_cast<uint2*>(sm + PV_AHI + off) = hi;
            *reinterpret_cast<uint2*>(sm + PV_ALO + off) = lo;
        }
        #pragma unroll
        for (int it = 0; it < 16; it++) {
            int idx = it * 256 + tid;
            int k = idx >> 6, n = idx & 63;
            size_t base = (size_t)(b3 * KLL + kc + k) * HDD + h3 * DD + n;
            int off = n * GP + k * 2;
            *reinterpret_cast<u16*>(sm + PV_BHI + off) = g_v_h[base];
            *reinterpret_cast<u16*>(sm + PV_BLO + off) = g_v_l[base];
        }
        __syncthreads();
        #pragma unroll
        for (int ks = 0; ks < 4; ks++)
            warp_mma<GP>(sb, PV_AHI, PV_ALO, PV_BHI, PV_BLO, ks << 4, mw, nw, lane, acc);
        __syncthreads();
    }

    float* dst = g_pv[ksp];
    const int gid = lane >> 2, tg = lane & 3;
    #pragma unroll
    for (int i = 0; i < 2; i++)
        #pragma unroll
        for (int j = 0; j < 4; j++) {
            int c = nw * 32 + j * 8 + tg * 2;
            #pragma unroll
            for (int eh = 0; eh < 2; eh++) {
                int q = q0 + mw * 32 + i * 16 + gid + 8 * eh;
                *reinterpret_cast<float2*>(
                    dst + (size_t)(b3 * QLL + q) * HDD + h3 * DD + c) =
                    make_float2(acc[i][j][eh * 2 + 0], acc[i][j][eh * 2 + 1]);
            }
        }
}

// ---------------------------------------------------------------------------
// Launch
// ---------------------------------------------------------------------------
extern "C" void kernel_launch(void* const* d_in, const int* in_sizes, int n_in,
                              void* d_out, int out_size)
{
    (void)in_sizes; (void)n_in; (void)out_size;

    const float*  Q    = (const float*)d_in[0];
    const float*  Kin  = (const float*)d_in[1];
    const float*  Vin  = (const float*)d_in[2];
    const float*  pos  = (const float*)d_in[3];
    const float*  rwb  = (const float*)d_in[4];
    const float*  rrb  = (const float*)d_in[5];
    const mask_t* mask = (const mask_t*)d_in[6];
    const float*  Wq = (const float*)d_in[8];
    const float*  bq = (const float*)d_in[9];
    const float*  Wk = (const float*)d_in[10];
    const float*  bk = (const float*)d_in[11];
    const float*  Wv = (const float*)d_in[12];
    const float*  bv = (const float*)d_in[13];
    const float*  Wr = (const float*)d_in[14];
    const float*  Wo = (const float*)d_in[15];
    const float*  bo = (const float*)d_in[16];

    float* out  = (float*)d_out;
    float* prob = out + (size_t)BB * QLL * EE;

    u16 *xh, *xl, *wh, *wl;
    u16 *qwh, *qwl, *qrh, *qrl, *kh, *kl, *vh, *vl, *rh, *rl, *vech, *vecl;
    float *ps; u8 *bits;
    cudaGetSymbolAddress((void**)&xh, g_x_h);
    cudaGetSymbolAddress((void**)&xl, g_x_l);
    cudaGetSymbolAddress((void**)&wh, g_w_h);
    cudaGetSymbolAddress((void**)&wl, g_w_l);
    cudaGetSymbolAddress((void**)&qwh, g_qw_h);
    cudaGetSymbolAddress((void**)&qwl, g_qw_l);
    cudaGetSymbolAddress((void**)&qrh, g_qr_h);
    cudaGetSymbolAddress((void**)&qrl, g_qr_l);
    cudaGetSymbolAddress((void**)&kh,  g_k_h);
    cudaGetSymbolAddress((void**)&kl,  g_k_l);
    cudaGetSymbolAddress((void**)&vh,  g_v_h);
    cudaGetSymbolAddress((void**)&vl,  g_v_l);
    cudaGetSymbolAddress((void**)&rh,  g_r_h);
    cudaGetSymbolAddress((void**)&rl,  g_r_l);
    cudaGetSymbolAddress((void**)&vech, g_vec_h);
    cudaGetSymbolAddress((void**)&vecl, g_vec_l);
    cudaGetSymbolAddress((void**)&ps,  g_s);
    cudaGetSymbolAddress((void**)&bits, g_bits);

    cudaFuncSetAttribute(tgemm,     cudaFuncAttributeMaxDynamicSharedMemorySize, T2_TOTAL);
    cudaFuncSetAttribute(tscore,    cudaFuncAttributeMaxDynamicSharedMemorySize, TS_TOTAL);
    cudaFuncSetAttribute(pv_kernel, cudaFuncAttributeMaxDynamicSharedMemorySize, PV_TOTAL);

    const dim3 blk(256);

    // Converts + mask pack
    cvt<<<(2048 * 768) / 1024, blk>>>(Q,   xh + XQ, xl + XQ, 2048 * 768);
    cvt<<<(4096 * 768) / 1024, blk>>>(Kin, xh + XK, xl + XK, 4096 * 768);
    cvt<<<(4096 * 768) / 1024, blk>>>(Vin, xh + XV, xl + XV, 4096 * 768);
    cvt<<<(2048 * 768) / 1024, blk>>>(pos, xh + XR, xl + XR, 2048 * 768);
    dim3 tgrid(24, 24), tblk(32, 8);
    cvtT<<<tgrid, tblk>>>(Wq, wh + WQO, wl + WQO);
    cvtT<<<tgrid, tblk>>>(Wk, wh + WKO, wl + WKO);
    cvtT<<<tgrid, tblk>>>(Wv, wh + WVO, wl + WVO);
    cvtT<<<tgrid, tblk>>>(Wr, wh + WRO, wl + WRO);
    cvtT<<<tgrid, tblk>>>(Wo, wh + WOO, wl + WOO);
    packmask<<<(BB * QLL * KLL / 8) / 256, blk>>>(mask, bits);

    // Projections
    tgemm<<<dim3(12, 16), blk, T2_TOTAL>>>(
        xh + XQ, xl + XQ, EE, wh + WQO, wl + WQO, EE, bq, 2,
        nullptr, qwh, qwl, qrh, qrl, rwb, rrb, HDD, EE);
    tgemm<<<dim3(12, 32), blk, T2_TOTAL>>>(
        xh + XK, xl + XK, EE, wh + WKO, wl + WKO, EE, bk, 1,
        nullptr, kh, kl, nullptr, nullptr, nullptr, nullptr, HDD, EE);
    tgemm<<<dim3(12, 32), blk, T2_TOTAL>>>(
        xh + XV, xl + XV, EE, wh + WVO, wl + WVO, EE, bv, 1,
        nullptr, vh, vl, nullptr, nullptr, nullptr, nullptr, HDD, EE);
    tgemm<<<dim3(12, 16), blk, T2_TOTAL>>>(
        xh + XR, xl + XR, EE, wh + WRO, wl + WRO, EE, nullptr, 1,
        nullptr, rh, rl, nullptr, nullptr, nullptr, nullptr, HDD, EE);

    // Scores (raw, scaled), 3-way k-split
    tscore<<<dim3(3, QLL / 128, BB * HH), blk, TS_TOTAL>>>();

    // Softmax (mask applied here) -> prob
    softmax_kernel<<<BB * HH * QLL, blk>>>(ps, prob);

    // PV (3-way k-split) + reduce/split
    pv_kernel<<<dim3(3, QLL / 128, BB * HH), blk, PV_TOTAL>>>(prob);
    vecfin<<<(BB * QLL * HDD) / 1024, blk>>>(vech, vecl);

    // Output projection
    tgemm<<<dim3(12, 16), blk, T2_TOTAL>>>(
        vech, vecl, HDD, wh + WOO, wl + WOO, HDD, bo, 0,
        out, nullptr, nullptr, nullptr, nullptr, nullptr, nullptr, EE, HDD);
}

// round 10
// speedup vs baseline: 1.6965x; 1.1063x over previous
#include <cuda_runtime.h>
#include <cuda_bf16.h>
#include <stdint.h>

// ---------------------------------------------------------------------------
// Problem constants
// ---------------------------------------------------------------------------
#define BB   2
#define HH   12
#define DD   64
#define EE   768
#define QLL  1024
#define KLL  2048
#define HDD  768
#define SCALEF 0.125f
typedef int mask_t;
typedef unsigned short u16;

// ---------------------------------------------------------------------------
// Scratch (device globals)
// ---------------------------------------------------------------------------
#define XQ 0
#define XK ((size_t)2048 * 768)
#define XV ((size_t)6144 * 768)
#define XR ((size_t)10240 * 768)
__device__ u16 g_x_h[(size_t)12288 * 768];
__device__ u16 g_x_l[(size_t)12288 * 768];
#define WQO ((size_t)0)
#define WKO ((size_t)1 * 768 * 768)
#define WVO ((size_t)2 * 768 * 768)
#define WRO ((size_t)3 * 768 * 768)
#define WOO ((size_t)4 * 768 * 768)
__device__ u16 g_w_h[(size_t)5 * 768 * 768];
__device__ u16 g_w_l[(size_t)5 * 768 * 768];
__device__ u16 g_qw_h[(size_t)BB * QLL * HDD];
__device__ u16 g_qw_l[(size_t)BB * QLL * HDD];
__device__ u16 g_qr_h[(size_t)BB * QLL * HDD];
__device__ u16 g_qr_l[(size_t)BB * QLL * HDD];
__device__ u16 g_k_h [(size_t)BB * KLL * HDD];
__device__ u16 g_k_l [(size_t)BB * KLL * HDD];
__device__ u16 g_v_h [(size_t)BB * KLL * HDD];
__device__ u16 g_v_l [(size_t)BB * KLL * HDD];
__device__ u16 g_r_h [(size_t)KLL * HDD];
__device__ u16 g_r_l [(size_t)KLL * HDD];
__device__ u16 g_vec_h[(size_t)BB * QLL * HDD];
__device__ u16 g_vec_l[(size_t)BB * QLL * HDD];
__device__ float g_pv[3][(size_t)BB * QLL * HDD];
__device__ float g_s[(size_t)BB * HH * QLL * KLL];

// ---------------------------------------------------------------------------
// Primitives
// ---------------------------------------------------------------------------
__device__ __forceinline__ uint32_t smem_u32(const void* p) {
    uint32_t a;
    asm("{ .reg .u64 t; cvta.to.shared.u64 t, %1; cvt.u32.u64 %0, t; }" : "=r"(a) : "l"(p));
    return a;
}
__device__ __forceinline__ void ldsm4(uint32_t& r0, uint32_t& r1, uint32_t& r2, uint32_t& r3,
                                      uint32_t a) {
    asm volatile("ldmatrix.sync.aligned.m8n8.x4.shared.b16 {%0,%1,%2,%3}, [%4];"
                 : "=r"(r0), "=r"(r1), "=r"(r2), "=r"(r3) : "r"(a));
}
__device__ __forceinline__ void mma16816(float* c, const uint32_t* a, const uint32_t* b) {
    asm volatile("mma.sync.aligned.m16n8k16.row.col.f32.bf16.bf16.f32 "
                 "{%0,%1,%2,%3}, {%4,%5,%6,%7}, {%8,%9}, {%0,%1,%2,%3};"
                 : "+f"(c[0]), "+f"(c[1]), "+f"(c[2]), "+f"(c[3])
                 : "r"(a[0]), "r"(a[1]), "r"(a[2]), "r"(a[3]), "r"(b[0]), "r"(b[1]));
}
__device__ __forceinline__ void cpa16(uint32_t dst, const void* src) {
    asm volatile("cp.async.cg.shared.global [%0], [%1], 16;" :: "r"(dst), "l"(src));
}
#define CP_COMMIT() asm volatile("cp.async.commit_group;" ::: "memory")
#define CP_WAIT(n)  asm volatile("cp.async.wait_group %0;" :: "n"(n) : "memory")

__device__ __forceinline__ void split_bf16(float x, u16& h, u16& l) {
    __nv_bfloat16 hb = __float2bfloat16(x);
    h = __bfloat16_as_ushort(hb);
    l = __bfloat16_as_ushort(__float2bfloat16(x - __bfloat162float(hb)));
}
__device__ __forceinline__ void split4(float4 v, uint2& hi, uint2& lo) {
    u16 h0, h1, h2, h3, l0, l1, l2, l3;
    split_bf16(v.x, h0, l0); split_bf16(v.y, h1, l1);
    split_bf16(v.z, h2, l2); split_bf16(v.w, h3, l3);
    hi = make_uint2((uint32_t)h0 | ((uint32_t)h1 << 16), (uint32_t)h2 | ((uint32_t)h3 << 16));
    lo = make_uint2((uint32_t)l0 | ((uint32_t)l1 << 16), (uint32_t)l2 | ((uint32_t)l3 << 16));
}

template<int P>
__device__ __forceinline__ void warp_mma(uint32_t sb, uint32_t aHi, uint32_t aLo,
                                         uint32_t bHi, uint32_t bLo,
                                         int kcc, int mw, int nw, int lane,
                                         float acc[2][4][4])
{
    uint32_t ah[2][4], al[2][4], bh[4][2], bl[4][2];
    #pragma unroll
    for (int i = 0; i < 2; i++) {
        int row = mw * 32 + i * 16 + (lane & 15);
        int col = kcc + ((lane >> 4) << 3);
        uint32_t off = (uint32_t)(row * P + col * 2);
        ldsm4(ah[i][0], ah[i][1], ah[i][2], ah[i][3], sb + aHi + off);
        ldsm4(al[i][0], al[i][1], al[i][2], al[i][3], sb + aLo + off);
    }
    #pragma unroll
    for (int jj = 0; jj < 2; jj++) {
        int n = nw * 32 + jj * 16 + ((lane >> 4) << 3) + (lane & 7);
        int k = kcc + (((lane >> 3) & 1) << 3);
        uint32_t off = (uint32_t)(n * P + k * 2);
        ldsm4(bh[jj*2][0], bh[jj*2][1], bh[jj*2+1][0], bh[jj*2+1][1], sb + bHi + off);
        ldsm4(bl[jj*2][0], bl[jj*2][1], bl[jj*2+1][0], bl[jj*2+1][1], sb + bLo + off);
    }
    #pragma unroll
    for (int i = 0; i < 2; i++)
        #pragma unroll
        for (int j = 0; j < 4; j++)
            mma16816(acc[i][j], ah[i], bh[j]);
    #pragma unroll
    for (int i = 0; i < 2; i++)
        #pragma unroll
        for (int j = 0; j < 4; j++)
            mma16816(acc[i][j], ah[i], bl[j]);
    #pragma unroll
    for (int i = 0; i < 2; i++)
        #pragma unroll
        for (int j = 0; j < 4; j++)
            mma16816(acc[i][j], al[i], bh[j]);
}

// ---------------------------------------------------------------------------
// Convert kernels
// ---------------------------------------------------------------------------
__global__ void cvt(const float* __restrict__ s, u16* __restrict__ dh,
                    u16* __restrict__ dl, int n)
{
    int i = (blockIdx.x * blockDim.x + threadIdx.x) * 4;
    if (i >= n) return;
    float4 v = *reinterpret_cast<const float4*>(s + i);
    uint2 h, l; split4(v, h, l);
    *reinterpret_cast<uint2*>(dh + i) = h;
    *reinterpret_cast<uint2*>(dl + i) = l;
}

__global__ void cvtT(const float* __restrict__ W, u16* __restrict__ th,
                     u16* __restrict__ tl)
{
    __shared__ float t[32][33];
    const int nb = blockIdx.x * 32, kb = blockIdx.y * 32;
    const int tx = threadIdx.x, ty = threadIdx.y;
    #pragma unroll
    for (int i = 0; i < 4; i++)
        t[ty + i * 8][tx] = W[(size_t)(kb + ty + i * 8) * 768 + nb + tx];
    __syncthreads();
    #pragma unroll
    for (int i = 0; i < 4; i++) {
        float v = t[tx][ty + i * 8];
        u16 h, l; split_bf16(v, h, l);
        size_t o = (size_t)(nb + ty + i * 8) * 768 + kb + tx;
        th[o] = h; tl[o] = l;
    }
}

__global__ void vecfin(u16* __restrict__ dh, u16* __restrict__ dl)
{
    int i = (blockIdx.x * blockDim.x + threadIdx.x) * 4;
    float4 a = *reinterpret_cast<const float4*>(&g_pv[0][i]);
    float4 b = *reinterpret_cast<const float4*>(&g_pv[1][i]);
    float4 c = *reinterpret_cast<const float4*>(&g_pv[2][i]);
    a.x += b.x + c.x; a.y += b.y + c.y; a.z += b.z + c.z; a.w += b.w + c.w;
    uint2 h, l; split4(a, h, l);
    *reinterpret_cast<uint2*>(dh + i) = h;
    *reinterpret_cast<uint2*>(dl + i) = l;
}

// ---------------------------------------------------------------------------
// Shared GEMM core: k-slab 32, 2-stage cp.async, 2 CTAs/SM, pitch 80B.
// ---------------------------------------------------------------------------
#define GP32 80
#define T2_AHI 0
#define T2_ALO (128 * GP32)
#define T2_BHI (2 * 128 * GP32)
#define T2_BLO (2 * 128 * GP32 + 64 * GP32)
#define T2_STAGE (2 * 128 * GP32 + 2 * 64 * GP32)  // 30720
#define T2_TOTAL (2 * T2_STAGE)                    // 61440

__device__ __forceinline__ void gemm_core(
    uint32_t sb, char* sm, int tid, int mw, int nw, int lane,
    const u16* Ah, const u16* Al, const u16* Bh, const u16* Bl,
    int m0, int n0, int K, float acc[2][4][4])
{
    const int nslab = K >> 5;
    auto issue = [&](int s, int st) {
        const uint32_t base = sb + st * T2_STAGE;
        const int k0 = s << 5;
        #pragma unroll
        for (int it = 0; it < 2; it++) {
            int id = it * 256 + tid;
            int m = id >> 2, c = id & 3;
            size_t src = (size_t)(m0 + m) * EE + k0 + c * 8;
            uint32_t dst = base + T2_AHI + m * GP32 + c * 16;
            cpa16(dst, Ah + src);
            cpa16(dst + (T2_ALO - T2_AHI), Al + src);
        }
        {
            int n = tid >> 2, c = tid & 3;
            size_t src = (size_t)(n0 + n) * EE + k0 + c * 8;
            uint32_t dst = base + T2_BHI + n * GP32 + c * 16;
            cpa16(dst, Bh + src);
            cpa16(dst + (T2_BLO - T2_BHI), Bl + src);
        }
    };

    issue(0, 0); CP_COMMIT();
    for (int s = 0; s < nslab; s++) {
        if (s + 1 < nslab) { issue(s + 1, (s + 1) & 1); CP_COMMIT(); CP_WAIT(1); }
        else               { CP_WAIT(0); }
        __syncthreads();
        const uint32_t st = (uint32_t)((s & 1) * T2_STAGE);
        #pragma unroll
        for (int ks = 0; ks < 2; ks++)
            warp_mma<GP32>(sb, st + T2_AHI, st + T2_ALO, st + T2_BHI, st + T2_BLO,
                           ks << 4, mw, nw, lane, acc);
        __syncthreads();
    }
}

// ---------------------------------------------------------------------------
// proj_all: all four projections in ONE launch.
//   z in [0,16)  : Q-proj (mode 2 -> qw,qr with rwb/rrb folded), bias bq
//   z in [16,48) : K-proj (mode 1 -> k),  bias bk
//   z in [48,80) : V-proj (mode 1 -> v),  bias bv
//   z in [80,96) : r-proj (mode 1 -> r),  no bias   (16 tiles: KLL rows!)
// ---------------------------------------------------------------------------
__global__ void __launch_bounds__(256, 2)
proj_all(const float* __restrict__ bq, const float* __restrict__ bk,
         const float* __restrict__ bv,
         const float* __restrict__ rwb, const float* __restrict__ rrb)
{
    extern __shared__ char sm[];
    const uint32_t sb = smem_u32(sm);
    const int tid = threadIdx.x, wid = tid >> 5, lane = tid & 31;
    const int mw = wid >> 1, nw = wid & 1;
    const int n0 = blockIdx.x << 6;
    const int z = blockIdx.z;

    const u16 *Ah, *Al, *Bh, *Bl;
    u16 *C1h, *C1l, *C2h = nullptr, *C2l = nullptr;
    const float *bias, *add1 = nullptr, *add2 = nullptr;
    int m0, mode;
    if (z < 16) {
        Ah = g_x_h + XQ; Al = g_x_l + XQ; Bh = g_w_h + WQO; Bl = g_w_l + WQO;
        C1h = g_qw_h; C1l = g_qw_l; C2h = g_qr_h; C2l = g_qr_l;
        bias = bq; add1 = rwb; add2 = rrb; mode = 2; m0 = z << 7;
    } else if (z < 48) {
        Ah = g_x_h + XK; Al = g_x_l + XK; Bh = g_w_h + WKO; Bl = g_w_l + WKO;
        C1h = g_k_h; C1l = g_k_l; bias = bk; mode = 1; m0 = (z - 16) << 7;
    } else if (z < 80) {
        Ah = g_x_h + XV; Al = g_x_l + XV; Bh = g_w_h + WVO; Bl = g_w_l + WVO;
        C1h = g_v_h; C1l = g_v_l; bias = bv; mode = 1; m0 = (z - 48) << 7;
    } else {
        Ah = g_x_h + XR; Al = g_x_l + XR; Bh = g_w_h + WRO; Bl = g_w_l + WRO;
        C1h = g_r_h; C1l = g_r_l; bias = nullptr; mode = 1; m0 = (z - 80) << 7;
    }

    float acc[2][4][4] = {};
    gemm_core(sb, sm, tid, mw, nw, lane, Ah, Al, Bh, Bl, m0, n0, EE, acc);

    const int gid = lane >> 2, tg = lane & 3;
    #pragma unroll
    for (int i = 0; i < 2; i++)
        #pragma unroll
        for (int j = 0; j < 4; j++) {
            int c = n0 + nw * 32 + j * 8 + tg * 2;
            float b0 = bias ? bias[c] : 0.f;
            float b1 = bias ? bias[c + 1] : 0.f;
            #pragma unroll
            for (int eh = 0; eh < 2; eh++) {
                int r = m0 + mw * 32 + i * 16 + gid + 8 * eh;
                size_t base = (size_t)r * HDD + c;
                float v0 = acc[i][j][eh * 2 + 0] + b0;
                float v1 = acc[i][j][eh * 2 + 1] + b1;
                if (mode == 1) {
                    u16 h0, l0, h1, l1;
                    split_bf16(v0, h0, l0); split_bf16(v1, h1, l1);
                    *reinterpret_cast<uint32_t*>(C1h + base) = (uint32_t)h0 | ((uint32_t)h1 << 16);
                    *reinterpret_cast<uint32_t*>(C1l + base) = (uint32_t)l0 | ((uint32_t)l1 << 16);
                } else {
                    u16 h0, l0, h1, l1;
                    split_bf16(v0 + add1[c], h0, l0); split_bf16(v1 + add1[c + 1], h1, l1);
                    *reinterpret_cast<uint32_t*>(C1h + base) = (uint32_t)h0 | ((uint32_t)h1 << 16);
                    *reinterpret_cast<uint32_t*>(C1l + base) = (uint32_t)l0 | ((uint32_t)l1 << 16);
                    split_bf16(v0 + add2[c], h0, l0); split_bf16(v1 + add2[c + 1], h1, l1);
                    *reinterpret_cast<uint32_t*>(C2h + base) = (uint32_t)h0 | ((uint32_t)h1 << 16);
                    *reinterpret_cast<uint32_t*>(C2l + base) = (uint32_t)l0 | ((uint32_t)l1 << 16);
                }
            }
        }
}

// ---------------------------------------------------------------------------
// out-proj: out = vec @ Wo + bo (fp32 out)
// ---------------------------------------------------------------------------
__global__ void __launch_bounds__(256, 2)
outproj(const float* __restrict__ bo, float* __restrict__ Cf)
{
    extern __shared__ char sm[];
    const uint32_t sb = smem_u32(sm);
    const int tid = threadIdx.x, wid = tid >> 5, lane = tid & 31;
    const int mw = wid >> 1, nw = wid & 1;
    const int m0 = blockIdx.y << 7;
    const int n0 = blockIdx.x << 6;

    float acc[2][4][4] = {};
    gemm_core(sb, sm, tid, mw, nw, lane, g_vec_h, g_vec_l,
              g_w_h + WOO, g_w_l + WOO, m0, n0, HDD, acc);

    const int gid = lane >> 2, tg = lane & 3;
    #pragma unroll
    for (int i = 0; i < 2; i++)
        #pragma unroll
        for (int j = 0; j < 4; j++) {
            int c = n0 + nw * 32 + j * 8 + tg * 2;
            float b0 = bo[c], b1 = bo[c + 1];
            #pragma unroll
            for (int eh = 0; eh < 2; eh++) {
                int r = m0 + mw * 32 + i * 16 + gid + 8 * eh;
                *reinterpret_cast<float2*>(Cf + (size_t)r * EE + c) =
                    make_float2(acc[i][j][eh * 2 + 0] + b0, acc[i][j][eh * 2 + 1] + b1);
            }
        }
}

// ---------------------------------------------------------------------------
// tscore: S = (A' * B'^T)*SCALE -> g_s (raw), 3-way k-split, 3-stage B ring
// ---------------------------------------------------------------------------
#define SP 272
#define TS_AHI 0
#define TS_ALO (128 * SP)
#define TS_B   (2 * 128 * SP)
#define TS_BSTG (2 * 64 * SP)
#define TS_BLOD (64 * SP)
#define TS_TOTAL (TS_B + 3 * TS_BSTG)     // 174080

__global__ void __launch_bounds__(256)
tscore()
{
    extern __shared__ char sm[];
    const uint32_t sb = smem_u32(sm);
    const int tid = threadIdx.x, wid = tid >> 5, lane = tid & 31;
    const int mw = wid >> 1, nw = wid & 1;
    const int gid = lane >> 2, tg = lane & 3;
    const int bh = blockIdx.z;
    const int b3 = bh / HH, h3 = bh % HH;
    const int mp = bh + BB;
    const int bu = mp / (HH + 1), hh = mp % (HH + 1);
    const int has_bd = (hh != 0);
    const int hm1 = hh - 1;
    const int q0 = blockIdx.y << 7;
    const int ksp = blockIdx.x;
    const int kt0 = (ksp * 32) / 3, kt1 = ((ksp + 1) * 32) / 3;

    #pragma unroll
    for (int it = 0; it < 8; it++) {
        int id = it * 256 + tid;
        int m = id >> 4, c = id & 15;
        uint4 hv, lv;
        if (c < 8) {
            size_t src = (size_t)(b3 * QLL + q0 + m) * HDD + h3 * DD + c * 8;
            hv = *reinterpret_cast<const uint4*>(g_qw_h + src);
            lv = *reinterpret_cast<const uint4*>(g_qw_l + src);
        } else if (has_bd) {
            size_t src = (size_t)(bu * QLL + q0 + m) * HDD + hm1 * DD + (c - 8) * 8;
            hv = *reinterpret_cast<const uint4*>(g_qr_h + src);
            lv = *reinterpret_cast<const uint4*>(g_qr_l + src);
        } else {
            hv = make_uint4(0u, 0u, 0u, 0u); lv = hv;
        }
        int off = m * SP + c * 16;
        *reinterpret_cast<uint4*>(sm + TS_AHI + off) = hv;
        *reinterpret_cast<uint4*>(sm + TS_ALO + off) = lv;
    }
    if (!has_bd) {
        uint4 z = make_uint4(0u, 0u, 0u, 0u);
        #pragma unroll
        for (int st3 = 0; st3 < 3; st3++)
            for (int id = tid; id < 64 * 8; id += 256) {
                int n = id >> 3, c = id & 7;
                int o = TS_B + st3 * TS_BSTG + n * SP + 128 + c * 16;
                *reinterpret_cast<uint4*>(sm + o) = z;
                *reinterpret_cast<uint4*>(sm + o + TS_BLOD) = z;
            }
    }

    auto issueB = [&](int kt, int st) {
        const uint32_t base = sb + TS_B + st * TS_BSTG;
        const int kc = kt << 6;
        const int nch = has_bd ? 16 : 8;
        const int tot = 64 * nch;
        for (int id = tid; id < tot; id += 256) {
            int n = id / nch, c = id % nch;
            uint32_t dst = base + n * SP + c * 16;
            if (c < 8) {
                size_t src = (size_t)(b3 * KLL + kc + n) * HDD + h3 * DD + c * 8;
                cpa16(dst, g_k_h + src);
                cpa16(dst + TS_BLOD, g_k_l + src);
            } else {
                size_t src = (size_t)(kc + n) * HDD + hm1 * DD + (c - 8) * 8;
                cpa16(dst, g_r_h + src);
                cpa16(dst + TS_BLOD, g_r_l + src);
            }
        }
    };

    // 3-stage prologue
    issueB(kt0, 0); CP_COMMIT();
    if (kt0 + 1 < kt1) issueB(kt0 + 1, 1);
    CP_COMMIT();

    for (int kt = kt0; kt < kt1; kt++) {
        const int stg = (kt - kt0) % 3;
        if (kt + 2 < kt1) { issueB(kt + 2, (kt - kt0 + 2) % 3); CP_COMMIT(); }
        else              { CP_COMMIT(); }
        const int ahead = (kt1 - 1 - kt) < 2 ? (kt1 - 1 - kt) : 2;
        if (ahead == 2)      CP_WAIT(2);
        else if (ahead == 1) CP_WAIT(1);
        else                 CP_WAIT(0);
        __syncthreads();

        float acc[2][4][4] = {};
        const uint32_t bst = (uint32_t)(TS_B + stg * TS_BSTG);
        #pragma unroll
        for (int ks = 0; ks < 8; ks++)
            warp_mma<SP>(sb, TS_AHI, TS_ALO, bst, bst + TS_BLOD,
                         ks << 4, mw, nw, lane, acc);

        const int kc = kt << 6;
        #pragma unroll
        for (int i = 0; i < 2; i++)
            #pragma unroll
            for (int j = 0; j < 4; j++) {
                int q = q0 + mw * 32 + i * 16 + gid;
                int c = kc + nw * 32 + j * 8 + tg * 2;
                const size_t srow0 = ((size_t)bh * QLL + q) * KLL + c;
                *reinterpret_cast<float2*>(g_s + srow0) =
                    make_float2(acc[i][j][0] * SCALEF, acc[i][j][1] * SCALEF);
                *reinterpret_cast<float2*>(g_s + srow0 + 8 * KLL) =
                    make_float2(acc[i][j][2] * SCALEF, acc[i][j][3] * SCALEF);
            }
        __syncthreads();
    }
}

// ---------------------------------------------------------------------------
// Softmax: reads int32 mask directly
// ---------------------------------------------------------------------------
__device__ __forceinline__ float warp_max(float v) {
    #pragma unroll
    for (int o = 16; o; o >>= 1) v = fmaxf(v, __shfl_xor_sync(0xffffffffu, v, o));
    return v;
}
__device__ __forceinline__ float warp_sum(float v) {
    #pragma unroll
    for (int o = 16; o; o >>= 1) v += __shfl_xor_sync(0xffffffffu, v, o);
    return v;
}

__global__ __launch_bounds__(256)
void softmax_kernel(const float* __restrict__ S, float* __restrict__ P,
                    const mask_t* __restrict__ mask)
{
    const size_t row = blockIdx.x;
    const int b3 = (int)(row / (HH * QLL));
    const int q  = (int)(row % QLL);
    const float* s = S + row * KLL;
    float*       p = P + row * KLL;
    const int tid = threadIdx.x;

    __shared__ float sh[8];
    const int wid = tid >> 5;
    const int lid = tid & 31;

    const mask_t* mrow = mask + ((size_t)b3 * QLL + q) * KLL + tid * 8;
    int4 mk0 = *reinterpret_cast<const int4*>(mrow);
    int4 mk1 = *reinterpret_cast<const int4*>(mrow + 4);

    float v[8];
    *reinterpret_cast<float4*>(v)     = *reinterpret_cast<const float4*>(s + tid * 8);
    *reinterpret_cast<float4*>(v + 4) = *reinterpret_cast<const float4*>(s + tid * 8 + 4);

    if (mk0.x) v[0] = -3.0e38f;
    if (mk0.y) v[1] = -3.0e38f;
    if (mk0.z) v[2] = -3.0e38f;
    if (mk0.w) v[3] = -3.0e38f;
    if (mk1.x) v[4] = -3.0e38f;
    if (mk1.y) v[5] = -3.0e38f;
    if (mk1.z) v[6] = -3.0e38f;
    if (mk1.w) v[7] = -3.0e38f;

    float m = -3.0e38f;
    #pragma unroll
    for (int i = 0; i < 8; i++) m = fmaxf(m, v[i]);
    float wm = warp_max(m);
    if (lid == 0) sh[wid] = wm;
    __syncthreads();
    if (wid == 0) {
        float t = (lid < 8) ? sh[lid] : -3.0e38f;
        t = warp_max(t);
        if (lid == 0) sh[0] = t;
    }
    __syncthreads();
    const float bm = sh[0];

    float lsum = 0.0f;
    #pragma unroll
    for (int i = 0; i < 8; i++) {
        v[i] = __expf(v[i] - bm);
        lsum += v[i];
    }
    float ws = warp_sum(lsum);
    __syncthreads();
    if (lid == 0) sh[wid] = ws;
    __syncthreads();
    if (wid == 0) {
        float t = (lid < 8) ? sh[lid] : 0.0f;
        t = warp_sum(t);
        if (lid == 0) sh[0] = t;
    }
    __syncthreads();
    const float inv = 1.0f / sh[0];

    #pragma unroll
    for (int i = 0; i < 8; i++) v[i] *= inv;
    *reinterpret_cast<float4*>(p + tid * 8)     = *reinterpret_cast<float4*>(v);
    *reinterpret_cast<float4*>(p + tid * 8 + 4) = *reinterpret_cast<float4*>(v + 4);
}

// ---------------------------------------------------------------------------
// pv: vec_partial[ksp] = prob tile @ V_h  (3-way k-split, fp32 out)
// ---------------------------------------------------------------------------
#define GP 144
#define PV_AHI 0
#define PV_ALO (128 * GP)
#define PV_BHI (2 * 128 * GP)
#define PV_BLO (2 * 128 * GP + 64 * GP)
#define PV_TOTAL (2 * 128 * GP + 2 * 64 * GP)   // 55296

__global__ void __launch_bounds__(256, 2)
pv_kernel(const float* __restrict__ prob)
{
    extern __shared__ char sm[];
    const uint32_t sb = smem_u32(sm);
    const int tid = threadIdx.x, wid = tid >> 5, lane = tid & 31;
    const int mw = wid >> 1, nw = wid & 1;
    const int bh = blockIdx.z;
    const int b3 = bh / HH, h3 = bh % HH;
    const int q0 = blockIdx.y << 7;
    const int ksp = blockIdx.x;
    const int kt0 = (ksp * 32) / 3, kt1 = ((ksp + 1) * 32) / 3;

    float acc[2][4][4] = {};

    for (int kt = kt0; kt < kt1; kt++) {
        const int kc = kt << 6;
        #pragma unroll
        for (int it = 0; it < 8; it++) {
            int idx = (it * 256 + tid) << 2;
            int m = idx >> 6, k = idx & 63;
            float4 p4 = *reinterpret_cast<const float4*>(
                prob + ((size_t)bh * QLL + q0 + m) * KLL + kc + k);
            uint2 hi, lo; split4(p4, hi, lo);
            int off = m * GP + k * 2;
            *reinterpret_cast<uint2*>(sm + PV_AHI + off) = hi;
            *reinterpret_cast<uint2*>(sm + PV_ALO + off) = lo;
        }
        #pragma unroll
        for (int it = 0; it < 16; it++) {
            int idx = it * 256 + tid;
            int k = idx >> 6, n = idx & 63;
            size_t base = (size_t)(b3 * KLL + kc + k) * HDD + h3 * DD + n;
            int off = n * GP + k * 2;
            *reinterpret_cast<u16*>(sm + PV_BHI + off) = g_v_h[base];
            *reinterpret_cast<u16*>(sm + PV_BLO + off) = g_v_l[base];
        }
        __syncthreads();
        #pragma unroll
        for (int ks = 0; ks < 4; ks++)
            warp_mma<GP>(sb, PV_AHI, PV_ALO, PV_BHI, PV_BLO, ks << 4, mw, nw, lane, acc);
        __syncthreads();
    }

    float* dst = g_pv[ksp];
    const int gid = lane >> 2, tg = lane & 3;
    #pragma unroll
    for (int i = 0; i < 2; i++)
        #pragma unroll
        for (int j = 0; j < 4; j++) {
            int c = nw * 32 + j * 8 + tg * 2;
            #pragma unroll
            for (int eh = 0; eh < 2; eh++) {
                int q = q0 + mw * 32 + i * 16 + gid + 8 * eh;
                *reinterpret_cast<float2*>(
                    dst + (size_t)(b3 * QLL + q) * HDD + h3 * DD + c) =
                    make_float2(acc[i][j][eh * 2 + 0], acc[i][j][eh * 2 + 1]);
            }
        }
}

// ---------------------------------------------------------------------------
// Launch
// ---------------------------------------------------------------------------
extern "C" void kernel_launch(void* const* d_in, const int* in_sizes, int n_in,
                              void* d_out, int out_size)
{
    (void)in_sizes; (void)n_in; (void)out_size;

    const float*  Q    = (const float*)d_in[0];
    const float*  Kin  = (const float*)d_in[1];
    const float*  Vin  = (const float*)d_in[2];
    const float*  pos  = (const float*)d_in[3];
    const float*  rwb  = (const float*)d_in[4];
    const float*  rrb  = (const float*)d_in[5];
    const mask_t* mask = (const mask_t*)d_in[6];
    const float*  Wq = (const float*)d_in[8];
    const float*  bq = (const float*)d_in[9];
    const float*  Wk = (const float*)d_in[10];
    const float*  bk = (const float*)d_in[11];
    const float*  Wv = (const float*)d_in[12];
    const float*  bv = (const float*)d_in[13];
    const float*  Wr = (const float*)d_in[14];
    const float*  Wo = (const float*)d_in[15];
    const float*  bo = (const float*)d_in[16];

    float* out  = (float*)d_out;
    float* prob = out + (size_t)BB * QLL * EE;

    u16 *xh, *xl, *wh, *wl, *vech, *vecl;
    float *ps;
    cudaGetSymbolAddress((void**)&xh, g_x_h);
    cudaGetSymbolAddress((void**)&xl, g_x_l);
    cudaGetSymbolAddress((void**)&wh, g_w_h);
    cudaGetSymbolAddress((void**)&wl, g_w_l);
    cudaGetSymbolAddress((void**)&vech, g_vec_h);
    cudaGetSymbolAddress((void**)&vecl, g_vec_l);
    cudaGetSymbolAddress((void**)&ps,  g_s);

    cudaFuncSetAttribute(proj_all,  cudaFuncAttributeMaxDynamicSharedMemorySize, T2_TOTAL);
    cudaFuncSetAttribute(outproj,   cudaFuncAttributeMaxDynamicSharedMemorySize, T2_TOTAL);
    cudaFuncSetAttribute(tscore,    cudaFuncAttributeMaxDynamicSharedMemorySize, TS_TOTAL);
    cudaFuncSetAttribute(pv_kernel, cudaFuncAttributeMaxDynamicSharedMemorySize, PV_TOTAL);

    const dim3 blk(256);

    // Converts
    cvt<<<(2048 * 768) / 1024, blk>>>(Q,   xh + XQ, xl + XQ, 2048 * 768);
    cvt<<<(4096 * 768) / 1024, blk>>>(Kin, xh + XK, xl + XK, 4096 * 768);
    cvt<<<(4096 * 768) / 1024, blk>>>(Vin, xh + XV, xl + XV, 4096 * 768);
    cvt<<<(2048 * 768) / 1024, blk>>>(pos, xh + XR, xl + XR, 2048 * 768);
    dim3 tgrid(24, 24), tblk(32, 8);
    cvtT<<<tgrid, tblk>>>(Wq, wh + WQO, wl + WQO);
    cvtT<<<tgrid, tblk>>>(Wk, wh + WKO, wl + WKO);
    cvtT<<<tgrid, tblk>>>(Wv, wh + WVO, wl + WVO);
    cvtT<<<tgrid, tblk>>>(Wr, wh + WRO, wl + WRO);
    cvtT<<<tgrid, tblk>>>(Wo, wh + WOO, wl + WOO);

    // All four projections in one launch (16+32+32+16 = 96 z-tiles, 1152 CTAs)
    proj_all<<<dim3(12, 1, 96), blk, T2_TOTAL>>>(bq, bk, bv, rwb, rrb);

    // Scores (raw, scaled), 3-way k-split, 3-stage ring
    tscore<<<dim3(3, QLL / 128, BB * HH), blk, TS_TOTAL>>>();

    // Softmax (mask read directly) -> prob
    softmax_kernel<<<BB * HH * QLL, blk>>>(ps, prob, mask);

    // PV (3-way k-split) + reduce/split
    pv_kernel<<<dim3(3, QLL / 128, BB * HH), blk, PV_TOTAL>>>(prob);
    vecfin<<<(BB * QLL * HDD) / 1024, blk>>>(vech, vecl);

    // Output projection
    outproj<<<dim3(12, 16), blk, T2_TOTAL>>>(bo, out);
}